// round 11
// baseline (speedup 1.0000x reference)
#include <cuda_runtime.h>
#include <cuda_bf16.h>
#include <stdint.h>
#include <math.h>

// ---------------- problem constants ----------------
#define TSTEPS 128
#define BATCH  1024
#define INDIM  47
#define HID    646
#define OUTDIM 5

// ---------------- tiling ----------------
#define MTILE 128
#define NTILE 64
#define KC    32                  // k-chunk (bf16)
#define NT    11                  // n-tiles over NPAD
#define TILES 88                  // per job
#define NPAD  704                 // W out-dim pad (n tiling)
#define HPAD  672                 // h k-dim pad (21 * 32)
#define XPAD  64
#define TPB   512                 // 16 warps: 4(m) x 4(n), warp tile 32x16
#define GRID  148                 // 1 CTA / SM

#define SST    40                 // smem row stride (bf16)
#define A_TILE (MTILE * SST)      // 5120 bf16
#define W_TILE (NTILE * SST)      // 2560 bf16
#define STAGE  (2 * A_TILE + 2 * W_TILE)   // 15360 bf16
#define NSTAGE 3
#define SMEM_BYTES (NSTAGE * STAGE * 2)    // 92160 B

// ---------------- device globals (no allocation allowed) ----------------
#define W_IH0_OFF 0
#define W_HH0_OFF (NPAD * XPAD)
#define W_IH1_OFF (W_HH0_OFF + NPAD * HPAD)
#define W_HH1_OFF (W_IH1_OFF + NPAD * HPAD)
#define W_TOT     (W_HH1_OFF + NPAD * HPAD)

#define NX ((long)TSTEPS * BATCH * XPAD)   // 8388608
#define NH (2 * BATCH * HPAD)              // 1376256

__device__ __align__(16) __nv_bfloat16 gx_h[NX];
__device__ __align__(16) __nv_bfloat16 gx_l[NX];
__device__ __align__(16) __nv_bfloat16 gW_h[W_TOT];
__device__ __align__(16) __nv_bfloat16 gW_l[W_TOT];
__device__ __align__(16) __nv_bfloat16 gh0_h[NH];
__device__ __align__(16) __nv_bfloat16 gh0_l[NH];
__device__ __align__(16) __nv_bfloat16 gh1_h[NH];
__device__ __align__(16) __nv_bfloat16 gh1_l[NH];
__device__ unsigned int g_counter[TSTEPS + 2];

// ---------------- helpers ----------------
__device__ __forceinline__ uint32_t pkbf(float lo, float hi) {
    uint32_t r;
    asm("cvt.rn.bf16x2.f32 %0, %1, %2;" : "=r"(r) : "f"(hi), "f"(lo));
    return r;
}
__device__ __forceinline__ float fast_tanh(float x) {
    float e = __expf(2.0f * x);
    return 1.0f - __fdividef(2.0f, e + 1.0f);
}
__device__ __forceinline__ void mma_bf16(float* d, const uint32_t a[4], const uint32_t* b) {
    asm volatile(
        "mma.sync.aligned.m16n8k16.row.col.f32.bf16.bf16.f32 "
        "{%0,%1,%2,%3}, {%4,%5,%6,%7}, {%8,%9}, {%0,%1,%2,%3};"
        : "+f"(d[0]), "+f"(d[1]), "+f"(d[2]), "+f"(d[3])
        : "r"(a[0]), "r"(a[1]), "r"(a[2]), "r"(a[3]), "r"(b[0]), "r"(b[1]));
}
#define LDSM_X4(R, addr) \
    asm volatile("ldmatrix.sync.aligned.m8n8.x4.shared.b16 {%0,%1,%2,%3}, [%4];" \
        : "=r"((R)[0]), "=r"((R)[1]), "=r"((R)[2]), "=r"((R)[3]) : "r"(addr))
#define CPA16(dst, src) \
    asm volatile("cp.async.cg.shared.global [%0], [%1], 16;" :: "r"(dst), "l"(src))
#define CPA_COMMIT() asm volatile("cp.async.commit_group;" ::: "memory")
#define CPA_WAIT0()  asm volatile("cp.async.wait_group 0;" ::: "memory")
#define CPA_WAIT1()  asm volatile("cp.async.wait_group 1;" ::: "memory")

// ---------------- single fused preprocessing kernel ----------------
__device__ __forceinline__ void split_one(__nv_bfloat16* dh, __nv_bfloat16* dl,
                                          const float* src, long i,
                                          int rreal, int creal, int cpad) {
    int r = (int)(i / cpad), c = (int)(i % cpad);
    float v = (r < rreal && c < creal) ? src[(long)r * creal + c] : 0.0f;
    __nv_bfloat16 hi = __float2bfloat16(v);
    dh[i] = hi;
    dl[i] = __float2bfloat16(v - __bfloat162float(hi));
}

#define NW0 ((long)NPAD * XPAD)    // 45056
#define NWH ((long)NPAD * HPAD)    // 473088

__global__ void prep_kernel(const float* __restrict__ xs,
                            const float* __restrict__ Wih0,
                            const float* __restrict__ Whh0,
                            const float* __restrict__ Wih1,
                            const float* __restrict__ Whh1) {
    long i = (long)blockIdx.x * blockDim.x + threadIdx.x;
    if (i < NX) split_one(gx_h, gx_l, xs, i, TSTEPS * BATCH, INDIM, XPAD);
    if (i < NW0)
        split_one(gW_h + W_IH0_OFF, gW_l + W_IH0_OFF, Wih0, i, HID, INDIM, XPAD);
    if (i < NWH) {
        split_one(gW_h + W_HH0_OFF, gW_l + W_HH0_OFF, Whh0, i, HID, HID, HPAD);
        split_one(gW_h + W_IH1_OFF, gW_l + W_IH1_OFF, Wih1, i, HID, HID, HPAD);
        split_one(gW_h + W_HH1_OFF, gW_l + W_HH1_OFF, Whh1, i, HID, HID, HPAD);
    }
    if (i < NH) {
        __nv_bfloat16 z = __float2bfloat16(0.0f);
        gh0_h[i] = z; gh0_l[i] = z; gh1_h[i] = z; gh1_l[i] = z;
    }
    if (i < TSTEPS + 2) g_counter[i] = 0u;
}

// ---------------- cell kernel ----------------
struct Seg {
    const __nv_bfloat16 *Ah, *Al;
    const __nv_bfloat16 *Wh, *Wl;
    int kpad, chunks;
};
struct Job {
    Seg s[2];
    const float *b1, *b2;
    __nv_bfloat16 *Ch, *Cl;
};

// cp.async for chunk c: 512 threads, 3 x 16B each (A hi 1, A lo 1, W 1)
__device__ __forceinline__ void issue_chunk(const Job& jb, int c, int m0, int n0,
                                            int tid, uint32_t st_u32) {
    const Seg& S = (c < jb.s[0].chunks) ? jb.s[0] : jb.s[1];
    const int cc = (c < jb.s[0].chunks) ? c : c - jb.s[0].chunks;
    const int col0 = cc * KC;
    const size_t kp = S.kpad;
    // A: 512 x 16B per half, one per thread
    const int ar = tid >> 2, ac = (tid & 3) * 8;
    const __nv_bfloat16* ah = S.Ah + (size_t)m0 * kp + col0;
    const __nv_bfloat16* al = S.Al + (size_t)m0 * kp + col0;
    CPA16(st_u32 + (ar * SST + ac) * 2,           ah + (size_t)ar * kp + ac);
    CPA16(st_u32 + (A_TILE + ar * SST + ac) * 2,  al + (size_t)ar * kp + ac);
    // W: 256 x 16B per half; threads <256 take hi, >=256 take lo
    const int wt = tid & 255;
    const int nr = wt >> 2, nc = (wt & 3) * 8;
    const __nv_bfloat16* wsrc = (tid < 256)
        ? S.Wh + (size_t)(n0 + nr) * kp + col0 + nc
        : S.Wl + (size_t)(n0 + nr) * kp + col0 + nc;
    const uint32_t wdst = st_u32 +
        ((tid < 256 ? 2 * A_TILE : 2 * A_TILE + W_TILE) + nr * SST + nc) * 2;
    CPA16(wdst, wsrc);
}

__global__ __launch_bounds__(TPB, 1) void cell_kernel(Job jH, Job jL,
                                                      int cidx, int ntiles) {
    extern __shared__ __nv_bfloat16 sm[];
    __shared__ float s_bias[NTILE];
    __shared__ unsigned int s_idx;

    const int tid = threadIdx.x, lane = tid & 31, wid = tid >> 5;
    const int wm0 = (wid & 3) * 32;      // warp m offset (4 m-warps)
    const int wn0 = (wid >> 2) * 16;     // warp n offset (4 n-warps, 16 cols each)
    const int r0 = lane >> 2;
    const int c0 = (lane & 3) * 2;

    const uint32_t sm_u32 = (uint32_t)__cvta_generic_to_shared(sm);

    const int lt = lane >> 3, lr = lane & 7;
    // A x4: tiles (i m-halves x k-halves): row = wm0+i*16+(lt&1)*8+lr, k = s*16+(lt>>1)*8
    uint32_t offA[2][2];
    #pragma unroll
    for (int i = 0; i < 2; i++)
        #pragma unroll
        for (int s = 0; s < 2; s++)
            offA[i][s] = ((wm0 + i * 16 + (lt & 1) * 8 + lr) * SST + s * 16 + (lt >> 1) * 8) * 2;
    // B x4: one load covers both n8 blocks: row = wn0+(lt>>1)*8+lr, k = s*16+(lt&1)*8
    // reg order: [j0k0, j0k8, j1k0, j1k8]
    uint32_t offB[2];
    #pragma unroll
    for (int s = 0; s < 2; s++)
        offB[s] = ((wn0 + (lt >> 1) * 8 + lr) * SST + s * 16 + (lt & 1) * 8) * 2;

    for (;;) {
        if (tid == 0) s_idx = atomicAdd(&g_counter[cidx], 1u);
        __syncthreads();   // s_idx handoff + all warps done with prev tile's smem/bias
        const unsigned int idx = s_idx;
        if (idx >= (unsigned int)ntiles) break;

        const Job& jb = (idx < TILES) ? jH : jL;
        const int tile = (idx < TILES) ? (int)idx : (int)idx - TILES;
        const int m0 = (tile / NT) * MTILE;
        const int n0 = (tile % NT) * NTILE;

        if (tid < NTILE) {
            int n = n0 + tid;
            s_bias[tid] = (n < HID) ? (jb.b1[n] + jb.b2[n]) : 0.0f;
        }

        // two accumulator sets: acc1 = ah*bh (chain 1), acc2 = ah*bl + al*bh (chain 2)
        float acc1[2][2][4] = {};
        float acc2[2][2][4] = {};
        const int nch = jb.s[0].chunks + jb.s[1].chunks;

        issue_chunk(jb, 0, m0, n0, tid, sm_u32);
        CPA_COMMIT();
        issue_chunk(jb, 1, m0, n0, tid, sm_u32 + STAGE * 2);
        CPA_COMMIT();

        int bc = 0, bn = 2;
        for (int c = 0; c < nch; c++) {
            if (c + 1 < nch) CPA_WAIT1(); else CPA_WAIT0();
            __syncthreads();  // chunk c visible; buffer bn reusable
            if (c + 2 < nch) {
                issue_chunk(jb, c + 2, m0, n0, tid, sm_u32 + bn * STAGE * 2);
                CPA_COMMIT();
            }

            const uint32_t sb = sm_u32 + bc * STAGE * 2;
            #pragma unroll
            for (int s = 0; s < 2; s++) {
                uint32_t ah[2][4], al[2][4], bh[4], bl[4];
                #pragma unroll
                for (int i = 0; i < 2; i++) {
                    LDSM_X4(ah[i], sb + offA[i][s]);
                    LDSM_X4(al[i], sb + offA[i][s] + A_TILE * 2);
                }
                LDSM_X4(bh, sb + offB[s] + 2 * A_TILE * 2);
                LDSM_X4(bl, sb + offB[s] + (2 * A_TILE + W_TILE) * 2);
                #pragma unroll
                for (int i = 0; i < 2; i++)
                    #pragma unroll
                    for (int j = 0; j < 2; j++) {
                        mma_bf16(acc1[i][j], ah[i], &bh[j * 2]);
                        mma_bf16(acc2[i][j], ah[i], &bl[j * 2]);
                        mma_bf16(acc2[i][j], al[i], &bh[j * 2]);
                    }
            }
            bc = (bc == NSTAGE - 1) ? 0 : bc + 1;
            bn = (bn == NSTAGE - 1) ? 0 : bn + 1;
        }

        // epilogue: combine terms, bias + tanh, store bf16 hi/lo pairs
        #pragma unroll
        for (int i = 0; i < 2; i++) {
            const int grow = m0 + wm0 + i * 16 + r0;
            #pragma unroll
            for (int j = 0; j < 2; j++) {
                const int col = wn0 + j * 8 + c0;
                if (n0 + col >= HPAD) continue;
                const float bv0 = s_bias[col], bv1 = s_bias[col + 1];
                const size_t o0 = (size_t)grow * HPAD + n0 + col;
                const size_t o1 = (size_t)(grow + 8) * HPAD + n0 + col;
                float t00 = fast_tanh(acc1[i][j][0] + acc2[i][j][0] + bv0);
                float t01 = fast_tanh(acc1[i][j][1] + acc2[i][j][1] + bv1);
                float t10 = fast_tanh(acc1[i][j][2] + acc2[i][j][2] + bv0);
                float t11 = fast_tanh(acc1[i][j][3] + acc2[i][j][3] + bv1);
                uint32_t u0 = pkbf(t00, t01);
                uint32_t u1 = pkbf(t10, t11);
                *(uint32_t*)(jb.Ch + o0) = u0;
                *(uint32_t*)(jb.Ch + o1) = u1;
                float s00 = t00 - __uint_as_float(u0 << 16);
                float s01 = t01 - __uint_as_float(u0 & 0xFFFF0000u);
                float s10 = t10 - __uint_as_float(u1 << 16);
                float s11 = t11 - __uint_as_float(u1 & 0xFFFF0000u);
                *(uint32_t*)(jb.Cl + o0) = pkbf(s00, s01);
                *(uint32_t*)(jb.Cl + o1) = pkbf(s10, s11);
            }
        }
    }
}

// ---------------- classifier ----------------
__global__ void classifier_kernel(const __nv_bfloat16* __restrict__ hh,
                                  const __nv_bfloat16* __restrict__ hl,
                                  const float* __restrict__ Wout,
                                  const float* __restrict__ bout,
                                  float* __restrict__ out) {
    int warp = (blockIdx.x * blockDim.x + threadIdx.x) >> 5;
    int lane = threadIdx.x & 31;
    if (warp >= BATCH * OUTDIM) return;
    int b = warp / OUTDIM, o = warp % OUTDIM;
    const __nv_bfloat16* rh = hh + (size_t)b * HPAD;
    const __nv_bfloat16* rl = hl + (size_t)b * HPAD;
    const float* wr = Wout + (size_t)o * HID;
    float s = 0.0f;
    for (int k = lane; k < HID; k += 32)
        s += (__bfloat162float(rh[k]) + __bfloat162float(rl[k])) * wr[k];
    #pragma unroll
    for (int off = 16; off; off >>= 1) s += __shfl_down_sync(0xffffffff, s, off);
    if (lane == 0) out[b * OUTDIM + o] = s + bout[o];
}

// ---------------- host ----------------
extern "C" void kernel_launch(void* const* d_in, const int* in_sizes, int n_in,
                              void* d_out, int out_size) {
    const float* xs   = (const float*)d_in[0];
    const float* Wih0 = (const float*)d_in[1];
    const float* Whh0 = (const float*)d_in[2];
    const float* bih0 = (const float*)d_in[3];
    const float* bhh0 = (const float*)d_in[4];
    const float* Wih1 = (const float*)d_in[5];
    const float* Whh1 = (const float*)d_in[6];
    const float* bih1 = (const float*)d_in[7];
    const float* bhh1 = (const float*)d_in[8];
    const float* Wout = (const float*)d_in[9];
    const float* bout = (const float*)d_in[10];
    float* out = (float*)d_out;

    static int attr_done = 0;
    if (!attr_done) {
        cudaFuncSetAttribute(cell_kernel, cudaFuncAttributeMaxDynamicSharedMemorySize,
                             SMEM_BYTES);
        attr_done = 1;
    }

    void* p;
    __nv_bfloat16 *xh, *xl, *wh, *wl, *h0h, *h0l, *h1h, *h1l;
    cudaGetSymbolAddress(&p, gx_h);  xh  = (__nv_bfloat16*)p;
    cudaGetSymbolAddress(&p, gx_l);  xl  = (__nv_bfloat16*)p;
    cudaGetSymbolAddress(&p, gW_h);  wh  = (__nv_bfloat16*)p;
    cudaGetSymbolAddress(&p, gW_l);  wl  = (__nv_bfloat16*)p;
    cudaGetSymbolAddress(&p, gh0_h); h0h = (__nv_bfloat16*)p;
    cudaGetSymbolAddress(&p, gh0_l); h0l = (__nv_bfloat16*)p;
    cudaGetSymbolAddress(&p, gh1_h); h1h = (__nv_bfloat16*)p;
    cudaGetSymbolAddress(&p, gh1_l); h1l = (__nv_bfloat16*)p;

    prep_kernel<<<(unsigned)((NX + 255) / 256), 256>>>(xs, Wih0, Whh0, Wih1, Whh1);

    const size_t HP = (size_t)BATCH * HPAD;
    const size_t XT = (size_t)BATCH * XPAD;
    const int XCHN = XPAD / KC;   // 2
    const int HCHN = HPAD / KC;   // 21

    // t = 0: layer0 only
    {
        Job j0;
        j0.s[0] = { xh, xl, wh + W_IH0_OFF, wl + W_IH0_OFF, XPAD, XCHN };
        j0.s[1] = { h0h + HP, h0l + HP, wh + W_HH0_OFF, wl + W_HH0_OFF, HPAD, HCHN };
        j0.b1 = bih0; j0.b2 = bhh0;
        j0.Ch = h0h; j0.Cl = h0l;
        cell_kernel<<<GRID, TPB, SMEM_BYTES>>>(j0, j0, 0, TILES);
    }

    // t = 1..127: fused h0(t) || h1(t-1); heavy layer1 job first
    for (int t = 1; t < TSTEPS; t++) {
        const size_t pPrev = (size_t)((t - 1) & 1) * HP;
        const size_t pCur  = (size_t)(t & 1) * HP;
        Job j1;
        j1.s[0] = { h0h + pPrev, h0l + pPrev, wh + W_IH1_OFF, wl + W_IH1_OFF, HPAD, HCHN };
        j1.s[1] = { h1h + pCur,  h1l + pCur,  wh + W_HH1_OFF, wl + W_HH1_OFF, HPAD, HCHN };
        j1.b1 = bih1; j1.b2 = bhh1;
        j1.Ch = h1h + pPrev; j1.Cl = h1l + pPrev;
        Job j0;
        j0.s[0] = { xh + (size_t)t * XT, xl + (size_t)t * XT,
                    wh + W_IH0_OFF, wl + W_IH0_OFF, XPAD, XCHN };
        j0.s[1] = { h0h + pPrev, h0l + pPrev, wh + W_HH0_OFF, wl + W_HH0_OFF, HPAD, HCHN };
        j0.b1 = bih0; j0.b2 = bhh0;
        j0.Ch = h0h + pCur; j0.Cl = h0l + pCur;
        cell_kernel<<<GRID, TPB, SMEM_BYTES>>>(j1, j0, t, 2 * TILES);
    }

    // drain: h1(127)
    {
        Job jf;
        jf.s[0] = { h0h + HP, h0l + HP, wh + W_IH1_OFF, wl + W_IH1_OFF, HPAD, HCHN };
        jf.s[1] = { h1h, h1l, wh + W_HH1_OFF, wl + W_HH1_OFF, HPAD, HCHN };
        jf.b1 = bih1; jf.b2 = bhh1;
        jf.Ch = h1h + HP; jf.Cl = h1l + HP;
        cell_kernel<<<GRID, TPB, SMEM_BYTES>>>(jf, jf, TSTEPS, TILES);
    }

    classifier_kernel<<<(BATCH * OUTDIM * 32 + 255) / 256, 256>>>(
        h1h + HP, h1l + HP, Wout, bout, out);
}

// round 12
// speedup vs baseline: 1.3826x; 1.3826x over previous
#include <cuda_runtime.h>
#include <cuda_bf16.h>
#include <stdint.h>
#include <math.h>

// ---------------- problem constants ----------------
#define TSTEPS 128
#define BATCH  1024
#define INDIM  47
#define HID    646
#define OUTDIM 5

// ---------------- tiling ----------------
#define MTILE 128
#define NTILE 64
#define KC    64                  // k-chunk (bf16) = 128B row
#define NT    11                  // n-tiles (NPAD 704)
#define MT    8
#define TILES 88                  // per job
#define HPAD  704                 // h k-dim pad = NPAD (11 chunks of 64)
#define XPAD  64                  // x k-dim pad (1 chunk)
#define TPB   512                 // 16 warps: 4(m) x 4(n)
#define GRID  148

// tiled-block sizes (bytes)
#define A_HALF 16384              // 128 rows x 128B
#define A_BLK  32768              // hi + lo
#define W_HALF 8192               // 64 rows x 128B
#define W_BLK  16384
#define STAGE_B (A_BLK + W_BLK)   // 49152
#define NSTAGE 3
#define SMEM_BYTES (NSTAGE * STAGE_B + 1024)

#define SWZ(x) ((x) ^ (((x) >> 3) & 0x70))

// ---------------- device globals (pre-tiled, pre-swizzled; no allocation) ----
#define PSZ ((size_t)MT * NT * A_BLK)        // per-parity h bytes: 2883584
__device__ __align__(1024) char gx[(size_t)TSTEPS * MT * A_BLK];   // 32MB
__device__ __align__(1024) char gh0[2 * PSZ];
__device__ __align__(1024) char gh1[2 * PSZ];
__device__ __align__(1024) char gWih0[NT * 1 * W_BLK];             // 176KB
__device__ __align__(1024) char gWhh0[NT * NT * W_BLK];            // 1.9MB
__device__ __align__(1024) char gWih1[NT * NT * W_BLK];
__device__ __align__(1024) char gWhh1[NT * NT * W_BLK];
__device__ unsigned int g_counter[TSTEPS + 2];

// ---------------- PTX helpers ----------------
__device__ __forceinline__ uint32_t pkbf(float lo, float hi) {
    uint32_t r;
    asm("cvt.rn.bf16x2.f32 %0, %1, %2;" : "=r"(r) : "f"(hi), "f"(lo));
    return r;
}
__device__ __forceinline__ float fast_tanh(float x) {
    float e = __expf(2.0f * x);
    return 1.0f - __fdividef(2.0f, e + 1.0f);
}
__device__ __forceinline__ void mma_bf16(float* d, const uint32_t a[4], const uint32_t* b) {
    asm volatile(
        "mma.sync.aligned.m16n8k16.row.col.f32.bf16.bf16.f32 "
        "{%0,%1,%2,%3}, {%4,%5,%6,%7}, {%8,%9}, {%0,%1,%2,%3};"
        : "+f"(d[0]), "+f"(d[1]), "+f"(d[2]), "+f"(d[3])
        : "r"(a[0]), "r"(a[1]), "r"(a[2]), "r"(a[3]), "r"(b[0]), "r"(b[1]));
}
#define LDSM_X4(R, addr) \
    asm volatile("ldmatrix.sync.aligned.m8n8.x4.shared.b16 {%0,%1,%2,%3}, [%4];" \
        : "=r"((R)[0]), "=r"((R)[1]), "=r"((R)[2]), "=r"((R)[3]) : "r"(addr))
#define MBARRIER_INIT(addr, cnt) \
    asm volatile("mbarrier.init.shared.b64 [%0], %1;" :: "r"(addr), "r"(cnt) : "memory")
#define MBARRIER_EXPECT_TX(addr, bytes) \
    asm volatile("mbarrier.arrive.expect_tx.shared.b64 _, [%0], %1;" :: "r"(addr), "r"(bytes) : "memory")
#define MBARRIER_WAIT_PARITY(addr, par) do {                                        \
    uint32_t _mb = (addr), _pa = (par), _dn;                                        \
    asm volatile("{ .reg .pred p; mbarrier.try_wait.parity.acquire.cta.shared::cta.b64 p, [%1], %2; selp.b32 %0, 1, 0, p; }" \
        : "=r"(_dn) : "r"(_mb), "r"(_pa) : "memory");                               \
    if (!_dn) {                                                                     \
        asm volatile("{ .reg .pred P1; WL%=: mbarrier.try_wait.parity.acquire.cta.shared::cta.b64 P1, [%0], %1, 0x989680; @P1 bra.uni WD%=; bra.uni WL%=; WD%=: }" \
            :: "r"(_mb), "r"(_pa) : "memory");                                      \
    }                                                                               \
} while (0)
#define BULK_G2S(dst, src, bytes, mbar) \
    asm volatile("cp.async.bulk.shared::cluster.global.mbarrier::complete_tx::bytes [%0], [%1], %2, [%3];" \
        :: "r"(dst), "l"(src), "r"(bytes), "r"(mbar) : "memory")

// ---------------- preprocessing: split to bf16 hi/lo, tiled + SW128 layout ----
__device__ __forceinline__ void store_split(char* base, uint32_t off, float v, int half_b) {
    __nv_bfloat16 hi = __float2bfloat16(v);
    *(__nv_bfloat16*)(base + off) = hi;
    *(__nv_bfloat16*)(base + half_b + off) = __float2bfloat16(v - __bfloat162float(hi));
}

#define NXE ((long)TSTEPS * MT * 8192)      // 8388608 x elements
#define NWHE ((long)NT * NT * 4096)         // 495616 hh-type elements
#define NW0E ((long)NT * 4096)              // 45056 ih0 elements
#define NHZ ((long)2 * PSZ / 16)            // h zero uint4 count

__global__ void prep_kernel(const float* __restrict__ xs,
                            const float* __restrict__ Wih0,
                            const float* __restrict__ Whh0,
                            const float* __restrict__ Wih1,
                            const float* __restrict__ Whh1) {
    long i = (long)blockIdx.x * blockDim.x + threadIdx.x;
    if (i < NXE) {
        int bi = (int)(i >> 13), e = (int)(i & 8191);
        int t = bi >> 3, mt = bi & 7, r = e >> 6, k = e & 63;
        float v = (k < INDIM)
            ? xs[((size_t)t * BATCH + mt * 128 + r) * INDIM + k] : 0.0f;
        store_split(gx + (size_t)bi * A_BLK, SWZ(r * 128 + k * 2), v, A_HALF);
    }
    if (i < NWHE) {
        int nt = (int)(i / (NT * 4096)); int rem = (int)(i % (NT * 4096));
        int c = rem >> 12, e = rem & 4095, r = e >> 6, k = e & 63;
        int n = nt * 64 + r, kk = c * 64 + k;
        bool ok = (n < HID) && (kk < HID);
        size_t boff = ((size_t)nt * NT + c) * W_BLK;
        uint32_t soff = SWZ(r * 128 + k * 2);
        store_split(gWhh0 + boff, soff, ok ? Whh0[(size_t)n * HID + kk] : 0.0f, W_HALF);
        store_split(gWih1 + boff, soff, ok ? Wih1[(size_t)n * HID + kk] : 0.0f, W_HALF);
        store_split(gWhh1 + boff, soff, ok ? Whh1[(size_t)n * HID + kk] : 0.0f, W_HALF);
    }
    if (i < NW0E) {
        int nt = (int)(i >> 12), e = (int)(i & 4095), r = e >> 6, k = e & 63;
        int n = nt * 64 + r;
        float v = (n < HID && k < INDIM) ? Wih0[(size_t)n * INDIM + k] : 0.0f;
        store_split(gWih0 + (size_t)nt * W_BLK, SWZ(r * 128 + k * 2), v, W_HALF);
    }
    if (i < NHZ) {
        uint4 z = make_uint4(0, 0, 0, 0);
        ((uint4*)gh0)[i] = z;
        ((uint4*)gh1)[i] = z;
    }
    if (i < TSTEPS + 2) g_counter[i] = 0u;
}

// ---------------- cell kernel ----------------
struct Seg {
    const char* A;   // tiled A blocks: block (mt*chunks + c) * A_BLK
    const char* W;   // tiled W blocks: block (nt*chunks + c) * W_BLK
    int chunks;
};
struct Job {
    Seg s[2];
    const float *b1, *b2;
    char* C;         // h output base (parity region); block (mt*NT + nt)
};

__device__ __forceinline__ void issue_chunk(const Job& jb, int c, int mt, int nt,
                                            uint32_t stage, uint32_t mbar) {
    const Seg& S = (c < jb.s[0].chunks) ? jb.s[0] : jb.s[1];
    const int cc = (c < jb.s[0].chunks) ? c : c - jb.s[0].chunks;
    const char* Asrc = S.A + ((size_t)mt * S.chunks + cc) * A_BLK;
    const char* Wsrc = S.W + ((size_t)nt * S.chunks + cc) * W_BLK;
    MBARRIER_EXPECT_TX(mbar, STAGE_B);
    BULK_G2S(stage, Asrc, A_BLK, mbar);
    BULK_G2S(stage + A_BLK, Wsrc, W_BLK, mbar);
}

__global__ __launch_bounds__(TPB, 1) void cell_kernel(Job jH, Job jL,
                                                      int cidx, int ntiles) {
    extern __shared__ __align__(1024) char dyn[];
    __shared__ __align__(8) uint64_t s_mbar[NSTAGE];
    __shared__ float s_bias[NTILE];
    __shared__ unsigned int s_idx;

    const int tid = threadIdx.x, lane = tid & 31, wid = tid >> 5;
    const int wm0 = (wid & 3) * 32;      // warp m offset
    const int wn0 = (wid >> 2) * 16;     // warp n offset
    const int r0 = lane >> 2;
    const int c0 = (lane & 3) * 2;

    uint32_t dyn_u32;
    asm("{ .reg .u64 t; cvta.to.shared.u64 t, %1; cvt.u32.u64 %0, t; }"
        : "=r"(dyn_u32) : "l"(dyn));
    const uint32_t base = (dyn_u32 + 1023) & ~1023u;
    uint32_t mb_u32;
    asm("{ .reg .u64 t; cvta.to.shared.u64 t, %1; cvt.u32.u64 %0, t; }"
        : "=r"(mb_u32) : "l"(&s_mbar[0]));

    if (tid == 0) {
        MBARRIER_INIT(mb_u32 + 0, 1);
        MBARRIER_INIT(mb_u32 + 8, 1);
        MBARRIER_INIT(mb_u32 + 16, 1);
    }
    __syncthreads();

    // ldmatrix within-tile swizzled offsets (constant per thread)
    const int lt = lane >> 3, lr = lane & 7;
    uint32_t offA[2][4], offB[4];
    #pragma unroll
    for (int i = 0; i < 2; i++)
        #pragma unroll
        for (int s = 0; s < 4; s++) {
            int rA = wm0 + i * 16 + (lt & 1) * 8 + lr;
            int cb = s * 32 + (lt >> 1) * 16;
            offA[i][s] = SWZ((uint32_t)(rA * 128 + cb));
        }
    #pragma unroll
    for (int s = 0; s < 4; s++) {
        int rB = wn0 + (lt >> 1) * 8 + lr;
        int cb = s * 32 + (lt & 1) * 16;
        offB[s] = SWZ((uint32_t)(rB * 128 + cb)) + A_BLK;   // W hi region
    }

    int q = 0, qi = 0;   // consumed / issued chunk counters (persist across tiles)

    for (;;) {
        if (tid == 0) s_idx = atomicAdd(&g_counter[cidx], 1u);
        __syncthreads();   // s_idx handoff; all threads past prev tile's epilogue
        const unsigned int idx = s_idx;
        if (idx >= (unsigned int)ntiles) break;

        const Job& jb = (idx < TILES) ? jH : jL;
        const int tile = (idx < TILES) ? (int)idx : (int)idx - TILES;
        const int mt = tile / NT;
        const int nt = tile % NT;
        const int n0 = nt * 64;

        if (tid < NTILE) {
            int n = n0 + tid;
            s_bias[tid] = (n < HID) ? (jb.b1[n] + jb.b2[n]) : 0.0f;
        }

        const int nch = jb.s[0].chunks + jb.s[1].chunks;

        // prologue: 2 chunks in flight (their buffers are free: prior tile fully consumed)
        if (tid == 0) {
            issue_chunk(jb, 0, mt, nt, base + (qi % 3) * STAGE_B, mb_u32 + (qi % 3) * 8);
        }
        qi++;
        if (tid == 0) {
            issue_chunk(jb, 1, mt, nt, base + (qi % 3) * STAGE_B, mb_u32 + (qi % 3) * 8);
        }
        qi++;

        float acc1[2][2][4] = {};
        float acc2[2][2][4] = {};

        for (int c = 0; c < nch; c++) {
            MBARRIER_WAIT_PARITY(mb_u32 + (q % 3) * 8, (uint32_t)((q / 3) & 1));
            __syncthreads();   // all warps done with chunk q-1 -> buffer (q+2)%3 free
            if (c + 2 < nch) {
                if (tid == 0)
                    issue_chunk(jb, c + 2, mt, nt,
                                base + (qi % 3) * STAGE_B, mb_u32 + (qi % 3) * 8);
                qi++;
            }

            const uint32_t sb = base + (q % 3) * STAGE_B;
            #pragma unroll
            for (int s = 0; s < 4; s++) {
                uint32_t ah[2][4], al[2][4], bh[4], bl[4];
                #pragma unroll
                for (int i = 0; i < 2; i++) {
                    LDSM_X4(ah[i], sb + offA[i][s]);
                    LDSM_X4(al[i], sb + offA[i][s] + A_HALF);
                }
                LDSM_X4(bh, sb + offB[s]);
                LDSM_X4(bl, sb + offB[s] + W_HALF);
                #pragma unroll
                for (int i = 0; i < 2; i++)
                    #pragma unroll
                    for (int j = 0; j < 2; j++) {
                        mma_bf16(acc1[i][j], ah[i], &bh[j * 2]);
                        mma_bf16(acc2[i][j], ah[i], &bl[j * 2]);
                        mma_bf16(acc2[i][j], al[i], &bh[j * 2]);
                    }
            }
            q++;
        }

        // epilogue: combine, bias + tanh, write h in tiled+swizzled hi/lo layout
        char* cblk = jb.C + ((size_t)mt * NT + nt) * A_BLK;
        #pragma unroll
        for (int i = 0; i < 2; i++) {
            const int grow = wm0 + i * 16 + r0;          // tile-local row
            #pragma unroll
            for (int j = 0; j < 2; j++) {
                const int col = wn0 + j * 8 + c0;        // tile-local col (even)
                const float bv0 = s_bias[col], bv1 = s_bias[col + 1];
                const uint32_t o0 = SWZ((uint32_t)(grow * 128 + col * 2));
                const uint32_t o1 = SWZ((uint32_t)((grow + 8) * 128 + col * 2));
                float t00 = fast_tanh(acc1[i][j][0] + acc2[i][j][0] + bv0);
                float t01 = fast_tanh(acc1[i][j][1] + acc2[i][j][1] + bv1);
                float t10 = fast_tanh(acc1[i][j][2] + acc2[i][j][2] + bv0);
                float t11 = fast_tanh(acc1[i][j][3] + acc2[i][j][3] + bv1);
                uint32_t u0 = pkbf(t00, t01);
                uint32_t u1 = pkbf(t10, t11);
                *(uint32_t*)(cblk + o0) = u0;
                *(uint32_t*)(cblk + o1) = u1;
                float s00 = t00 - __uint_as_float(u0 << 16);
                float s01 = t01 - __uint_as_float(u0 & 0xFFFF0000u);
                float s10 = t10 - __uint_as_float(u1 << 16);
                float s11 = t11 - __uint_as_float(u1 & 0xFFFF0000u);
                *(uint32_t*)(cblk + A_HALF + o0) = pkbf(s00, s01);
                *(uint32_t*)(cblk + A_HALF + o1) = pkbf(s10, s11);
                // zero-init of acc for next tile
                #pragma unroll
                for (int z = 0; z < 4; z++) { acc1[i][j][z] = 0.f; acc2[i][j][z] = 0.f; }
            }
        }
    }
}

// ---------------- classifier (reads tiled h layout) ----------------
__global__ void classifier_kernel(const char* __restrict__ hbase,
                                  const float* __restrict__ Wout,
                                  const float* __restrict__ bout,
                                  float* __restrict__ out) {
    int warp = (blockIdx.x * blockDim.x + threadIdx.x) >> 5;
    int lane = threadIdx.x & 31;
    if (warp >= BATCH * OUTDIM) return;
    int b = warp / OUTDIM, o = warp % OUTDIM;
    const float* wr = Wout + (size_t)o * HID;
    float s = 0.0f;
    for (int k = lane; k < HID; k += 32) {
        size_t blk = ((size_t)(b >> 7) * NT + (k >> 6)) * A_BLK;
        uint32_t off = SWZ((uint32_t)(((b & 127) * 128) + (k & 63) * 2));
        float hv = __bfloat162float(*(const __nv_bfloat16*)(hbase + blk + off))
                 + __bfloat162float(*(const __nv_bfloat16*)(hbase + blk + A_HALF + off));
        s += hv * wr[k];
    }
    #pragma unroll
    for (int off = 16; off; off >>= 1) s += __shfl_down_sync(0xffffffff, s, off);
    if (lane == 0) out[b * OUTDIM + o] = s + bout[o];
}

// ---------------- host ----------------
extern "C" void kernel_launch(void* const* d_in, const int* in_sizes, int n_in,
                              void* d_out, int out_size) {
    const float* xs   = (const float*)d_in[0];
    const float* Wih0 = (const float*)d_in[1];
    const float* Whh0 = (const float*)d_in[2];
    const float* bih0 = (const float*)d_in[3];
    const float* bhh0 = (const float*)d_in[4];
    const float* Wih1 = (const float*)d_in[5];
    const float* Whh1 = (const float*)d_in[6];
    const float* bih1 = (const float*)d_in[7];
    const float* bhh1 = (const float*)d_in[8];
    const float* Wout = (const float*)d_in[9];
    const float* bout = (const float*)d_in[10];
    float* out = (float*)d_out;

    static int attr_done = 0;
    if (!attr_done) {
        cudaFuncSetAttribute(cell_kernel, cudaFuncAttributeMaxDynamicSharedMemorySize,
                             SMEM_BYTES);
        attr_done = 1;
    }

    void* p;
    char *xb, *h0b, *h1b, *wi0, *wh0, *wi1, *wh1;
    cudaGetSymbolAddress(&p, gx);    xb  = (char*)p;
    cudaGetSymbolAddress(&p, gh0);   h0b = (char*)p;
    cudaGetSymbolAddress(&p, gh1);   h1b = (char*)p;
    cudaGetSymbolAddress(&p, gWih0); wi0 = (char*)p;
    cudaGetSymbolAddress(&p, gWhh0); wh0 = (char*)p;
    cudaGetSymbolAddress(&p, gWih1); wi1 = (char*)p;
    cudaGetSymbolAddress(&p, gWhh1); wh1 = (char*)p;

    prep_kernel<<<(unsigned)((NXE + 255) / 256), 256>>>(xs, Wih0, Whh0, Wih1, Whh1);

    const size_t XB = (size_t)MT * A_BLK;    // per-timestep x bytes

    // t = 0: layer0 only  (h0(-1) = zeros at parity 1)
    {
        Job j0;
        j0.s[0] = { xb, wi0, 1 };
        j0.s[1] = { h0b + PSZ, wh0, NT };
        j0.b1 = bih0; j0.b2 = bhh0;
        j0.C = h0b;                          // parity 0
        cell_kernel<<<GRID, TPB, SMEM_BYTES>>>(j0, j0, 0, TILES);
    }

    // t = 1..127: fused h0(t) || h1(t-1); heavy layer1 job first
    for (int t = 1; t < TSTEPS; t++) {
        const size_t pPrev = (size_t)((t - 1) & 1) * PSZ;
        const size_t pCur  = (size_t)(t & 1) * PSZ;
        Job j1;   // h1(t-1) = g(h0(t-1), h1(t-2))
        j1.s[0] = { h0b + pPrev, wi1, NT };
        j1.s[1] = { h1b + pCur,  wh1, NT };
        j1.b1 = bih1; j1.b2 = bhh1;
        j1.C = h1b + pPrev;
        Job j0;   // h0(t) = f(x_t, h0(t-1))
        j0.s[0] = { xb + (size_t)t * XB, wi0, 1 };
        j0.s[1] = { h0b + pPrev, wh0, NT };
        j0.b1 = bih0; j0.b2 = bhh0;
        j0.C = h0b + pCur;
        cell_kernel<<<GRID, TPB, SMEM_BYTES>>>(j1, j0, t, 2 * TILES);
    }

    // drain: h1(127) = g(h0(127) [parity 1], h1(126) [parity 0]) -> parity 1
    {
        Job jf;
        jf.s[0] = { h0b + PSZ, wi1, NT };
        jf.s[1] = { h1b,       wh1, NT };
        jf.b1 = bih1; jf.b2 = bhh1;
        jf.C = h1b + PSZ;
        cell_kernel<<<GRID, TPB, SMEM_BYTES>>>(jf, jf, TSTEPS, TILES);
    }

    classifier_kernel<<<(BATCH * OUTDIM * 32 + 255) / 256, 256>>>(
        h1b + PSZ, Wout, bout, out);
}

// round 13
// speedup vs baseline: 1.6117x; 1.1657x over previous
#include <cuda_runtime.h>
#include <cuda_bf16.h>
#include <stdint.h>
#include <math.h>

// ---------------- problem constants ----------------
#define TSTEPS 128
#define BATCH  1024
#define INDIM  47
#define HID    646
#define OUTDIM 5

// ---------------- tiling ----------------
#define MTILE 128
#define NTILE 64
#define KC    64                  // k-chunk (bf16) = 128B row
#define NT    11                  // n-tiles (NPAD 704)
#define MT    8
#define TILES 88                  // per job
#define TPB   512                 // 16 warps: 4(m) x 4(n)
#define GRID  148

// tiled-block sizes (bytes)
#define A_HALF 16384              // 128 rows x 128B
#define A_BLK  32768              // hi + lo
#define W_HALF 8192               // 64 rows x 128B
#define W_BLK  16384
#define STAGE_B (A_BLK + W_BLK)   // 49152
#define NSTAGE 4
#define SMEM_BYTES (NSTAGE * STAGE_B + 1024)   // 197632

#define SWZ(x) ((x) ^ (((x) >> 3) & 0x70))

// ---------------- device globals (pre-tiled, pre-swizzled; no allocation) ----
#define PSZ ((size_t)MT * NT * A_BLK)        // per-parity h bytes
__device__ __align__(1024) char gx[(size_t)TSTEPS * MT * A_BLK];   // 32MB
__device__ __align__(1024) char gh0[2 * PSZ];
__device__ __align__(1024) char gh1[2 * PSZ];
__device__ __align__(1024) char gWih0[NT * 1 * W_BLK];
__device__ __align__(1024) char gWhh0[NT * NT * W_BLK];
__device__ __align__(1024) char gWih1[NT * NT * W_BLK];
__device__ __align__(1024) char gWhh1[NT * NT * W_BLK];
__device__ unsigned int g_counter[TSTEPS + 2];

// ---------------- PTX helpers ----------------
__device__ __forceinline__ uint32_t pkbf(float lo, float hi) {
    uint32_t r;
    asm("cvt.rn.bf16x2.f32 %0, %1, %2;" : "=r"(r) : "f"(hi), "f"(lo));
    return r;
}
__device__ __forceinline__ float fast_tanh(float x) {
    float e = __expf(2.0f * x);
    return 1.0f - __fdividef(2.0f, e + 1.0f);
}
__device__ __forceinline__ void mma_bf16(float* d, const uint32_t a[4], const uint32_t* b) {
    asm volatile(
        "mma.sync.aligned.m16n8k16.row.col.f32.bf16.bf16.f32 "
        "{%0,%1,%2,%3}, {%4,%5,%6,%7}, {%8,%9}, {%0,%1,%2,%3};"
        : "+f"(d[0]), "+f"(d[1]), "+f"(d[2]), "+f"(d[3])
        : "r"(a[0]), "r"(a[1]), "r"(a[2]), "r"(a[3]), "r"(b[0]), "r"(b[1]));
}
#define LDSM_X4(R, addr) \
    asm volatile("ldmatrix.sync.aligned.m8n8.x4.shared.b16 {%0,%1,%2,%3}, [%4];" \
        : "=r"((R)[0]), "=r"((R)[1]), "=r"((R)[2]), "=r"((R)[3]) : "r"(addr))
#define MBARRIER_INIT(addr, cnt) \
    asm volatile("mbarrier.init.shared.b64 [%0], %1;" :: "r"(addr), "r"(cnt) : "memory")
#define MBARRIER_EXPECT_TX(addr, bytes) \
    asm volatile("mbarrier.arrive.expect_tx.shared.b64 _, [%0], %1;" :: "r"(addr), "r"(bytes) : "memory")
#define MBARRIER_ARRIVE(addr) \
    asm volatile("mbarrier.arrive.shared.b64 _, [%0];" :: "r"(addr) : "memory")
#define MBARRIER_WAIT_PARITY(addr, par) do {                                        \
    uint32_t _mb = (addr), _pa = (par), _dn;                                        \
    asm volatile("{ .reg .pred p; mbarrier.try_wait.parity.acquire.cta.shared::cta.b64 p, [%1], %2; selp.b32 %0, 1, 0, p; }" \
        : "=r"(_dn) : "r"(_mb), "r"(_pa) : "memory");                               \
    if (!_dn) {                                                                     \
        asm volatile("{ .reg .pred P1; WL%=: mbarrier.try_wait.parity.acquire.cta.shared::cta.b64 P1, [%0], %1, 0x989680; @P1 bra.uni WD%=; bra.uni WL%=; WD%=: }" \
            :: "r"(_mb), "r"(_pa) : "memory");                                      \
    }                                                                               \
} while (0)
#define BULK_G2S(dst, src, bytes, mbar) \
    asm volatile("cp.async.bulk.shared::cluster.global.mbarrier::complete_tx::bytes [%0], [%1], %2, [%3];" \
        :: "r"(dst), "l"(src), "r"(bytes), "r"(mbar) : "memory")

// ---------------- preprocessing: split to bf16 hi/lo, tiled + SW128 layout ----
__device__ __forceinline__ void store_split(char* base, uint32_t off, float v, int half_b) {
    __nv_bfloat16 hi = __float2bfloat16(v);
    *(__nv_bfloat16*)(base + off) = hi;
    *(__nv_bfloat16*)(base + half_b + off) = __float2bfloat16(v - __bfloat162float(hi));
}

#define NXE ((long)TSTEPS * MT * 8192)
#define NWHE ((long)NT * NT * 4096)
#define NW0E ((long)NT * 4096)
#define NHZ ((long)2 * PSZ / 16)

__global__ void prep_kernel(const float* __restrict__ xs,
                            const float* __restrict__ Wih0,
                            const float* __restrict__ Whh0,
                            const float* __restrict__ Wih1,
                            const float* __restrict__ Whh1) {
    long i = (long)blockIdx.x * blockDim.x + threadIdx.x;
    if (i < NXE) {
        int bi = (int)(i >> 13), e = (int)(i & 8191);
        int t = bi >> 3, mt = bi & 7, r = e >> 6, k = e & 63;
        float v = (k < INDIM)
            ? xs[((size_t)t * BATCH + mt * 128 + r) * INDIM + k] : 0.0f;
        store_split(gx + (size_t)bi * A_BLK, SWZ(r * 128 + k * 2), v, A_HALF);
    }
    if (i < NWHE) {
        int nt = (int)(i / (NT * 4096)); int rem = (int)(i % (NT * 4096));
        int c = rem >> 12, e = rem & 4095, r = e >> 6, k = e & 63;
        int n = nt * 64 + r, kk = c * 64 + k;
        bool ok = (n < HID) && (kk < HID);
        size_t boff = ((size_t)nt * NT + c) * W_BLK;
        uint32_t soff = SWZ(r * 128 + k * 2);
        store_split(gWhh0 + boff, soff, ok ? Whh0[(size_t)n * HID + kk] : 0.0f, W_HALF);
        store_split(gWih1 + boff, soff, ok ? Wih1[(size_t)n * HID + kk] : 0.0f, W_HALF);
        store_split(gWhh1 + boff, soff, ok ? Whh1[(size_t)n * HID + kk] : 0.0f, W_HALF);
    }
    if (i < NW0E) {
        int nt = (int)(i >> 12), e = (int)(i & 4095), r = e >> 6, k = e & 63;
        int n = nt * 64 + r;
        float v = (n < HID && k < INDIM) ? Wih0[(size_t)n * INDIM + k] : 0.0f;
        store_split(gWih0 + (size_t)nt * W_BLK, SWZ(r * 128 + k * 2), v, W_HALF);
    }
    if (i < NHZ) {
        uint4 z = make_uint4(0, 0, 0, 0);
        ((uint4*)gh0)[i] = z;
        ((uint4*)gh1)[i] = z;
    }
    if (i < TSTEPS + 2) g_counter[i] = 0u;
}

// ---------------- cell kernel ----------------
struct Seg {
    const char* A;   // tiled A blocks: (mt*chunks + c) * A_BLK
    const char* W;   // tiled W blocks: (nt*chunks + c) * W_BLK
    int chunks;
};
struct Job {
    Seg s[2];
    const float *b1, *b2;
    char* C;
};

// producer: wait empty[stage], then expect_tx + 2 bulk copies into stage
__device__ __forceinline__ void issue_at(const Job& jb, int c, int mt, int nt,
                                         uint32_t base, uint32_t full_mb,
                                         uint32_t empty_mb, int g) {
    const int st = g & (NSTAGE - 1);
    const int rnd = g >> 2;
    // empty parity: round 0 passes immediately (virtual completion -1 has parity 1)
    MBARRIER_WAIT_PARITY(empty_mb + st * 8, (uint32_t)((rnd + 1) & 1));
    const Seg& S = (c < jb.s[0].chunks) ? jb.s[0] : jb.s[1];
    const int cc = (c < jb.s[0].chunks) ? c : c - jb.s[0].chunks;
    const char* Asrc = S.A + ((size_t)mt * S.chunks + cc) * A_BLK;
    const char* Wsrc = S.W + ((size_t)nt * S.chunks + cc) * W_BLK;
    const uint32_t stage = base + st * STAGE_B;
    const uint32_t fmb = full_mb + st * 8;
    MBARRIER_EXPECT_TX(fmb, STAGE_B);
    BULK_G2S(stage, Asrc, A_BLK, fmb);
    BULK_G2S(stage + A_BLK, Wsrc, W_BLK, fmb);
}

__global__ __launch_bounds__(TPB, 1) void cell_kernel(Job jH, Job jL,
                                                      int cidx, int ntiles) {
    extern __shared__ __align__(1024) char dyn[];
    __shared__ __align__(8) uint64_t s_mbar[2 * NSTAGE];   // full[0..3], empty[4..7]
    __shared__ float s_bias[NTILE];
    __shared__ unsigned int s_idx;

    const int tid = threadIdx.x, lane = tid & 31, wid = tid >> 5;
    const int wm0 = (wid & 3) * 32;
    const int wn0 = (wid >> 2) * 16;
    const int r0 = lane >> 2;
    const int c0 = (lane & 3) * 2;
    const bool producer = (tid == 0);

    uint32_t dyn_u32;
    asm("{ .reg .u64 t; cvta.to.shared.u64 t, %1; cvt.u32.u64 %0, t; }"
        : "=r"(dyn_u32) : "l"(dyn));
    const uint32_t base = (dyn_u32 + 1023) & ~1023u;
    uint32_t mb_u32;
    asm("{ .reg .u64 t; cvta.to.shared.u64 t, %1; cvt.u32.u64 %0, t; }"
        : "=r"(mb_u32) : "l"(&s_mbar[0]));
    const uint32_t full_mb = mb_u32;
    const uint32_t empty_mb = mb_u32 + 8 * NSTAGE;

    if (tid == 0) {
        #pragma unroll
        for (int s = 0; s < NSTAGE; s++) {
            MBARRIER_INIT(full_mb + s * 8, 1);     // tx-based
            MBARRIER_INIT(empty_mb + s * 8, 16);   // one arrive per warp
        }
    }
    __syncthreads();

    // ldmatrix within-tile swizzled offsets
    const int lt = lane >> 3, lr = lane & 7;
    uint32_t offA[2][4], offB[4];
    #pragma unroll
    for (int i = 0; i < 2; i++)
        #pragma unroll
        for (int s = 0; s < 4; s++) {
            int rA = wm0 + i * 16 + (lt & 1) * 8 + lr;
            int cb = s * 32 + (lt >> 1) * 16;
            offA[i][s] = SWZ((uint32_t)(rA * 128 + cb));
        }
    #pragma unroll
    for (int s = 0; s < 4; s++) {
        int rB = wn0 + (lt >> 1) * 8 + lr;
        int cb = s * 32 + (lt & 1) * 16;
        offB[s] = SWZ((uint32_t)(rB * 128 + cb)) + A_BLK;
    }

    int gq = 0;    // per-warp consumed-chunk cursor (global across tiles)
    int gqi = 0;   // producer issued-chunk cursor

    for (;;) {
        if (tid == 0) s_idx = atomicAdd(&g_counter[cidx], 1u);
        __syncthreads();   // s_idx handoff; all warps past prev tile's epilogue/bias
        const unsigned int idx = s_idx;
        if (idx >= (unsigned int)ntiles) break;

        const Job& jb = (idx < TILES) ? jH : jL;
        const int tile = (idx < TILES) ? (int)idx : (int)idx - TILES;
        const int mt = tile / NT;
        const int nt = tile % NT;
        const int n0 = nt * 64;

        if (tid < NTILE) {
            int n = n0 + tid;
            s_bias[tid] = (n < HID) ? (jb.b1[n] + jb.b2[n]) : 0.0f;
        }

        const int nch = jb.s[0].chunks + jb.s[1].chunks;

        // prologue: producer fills up to 3 stages ahead
        if (producer) {
            const int pro = (nch < NSTAGE - 1) ? nch : NSTAGE - 1;
            for (int c = 0; c < pro; c++) {
                issue_at(jb, c, mt, nt, base, full_mb, empty_mb, gqi);
                gqi++;
            }
        }

        float acc1[2][2][4] = {};
        float acc2[2][2][4] = {};

        for (int c = 0; c < nch; c++) {
            if (producer && c + NSTAGE - 1 < nch) {
                issue_at(jb, c + NSTAGE - 1, mt, nt, base, full_mb, empty_mb, gqi);
                gqi++;
            }
            const int st = gq & (NSTAGE - 1);
            const int rnd = gq >> 2;
            MBARRIER_WAIT_PARITY(full_mb + st * 8, (uint32_t)(rnd & 1));

            const uint32_t sb = base + st * STAGE_B;
            #pragma unroll
            for (int s = 0; s < 4; s++) {
                uint32_t ah[2][4], al[2][4], bh[4], bl[4];
                #pragma unroll
                for (int i = 0; i < 2; i++) {
                    LDSM_X4(ah[i], sb + offA[i][s]);
                    LDSM_X4(al[i], sb + offA[i][s] + A_HALF);
                }
                LDSM_X4(bh, sb + offB[s]);
                LDSM_X4(bl, sb + offB[s] + W_HALF);
                #pragma unroll
                for (int i = 0; i < 2; i++)
                    #pragma unroll
                    for (int j = 0; j < 2; j++) {
                        mma_bf16(acc1[i][j], ah[i], &bh[j * 2]);
                        mma_bf16(acc2[i][j], ah[i], &bl[j * 2]);
                        mma_bf16(acc2[i][j], al[i], &bh[j * 2]);
                    }
            }
            // last ldmatrix.sync converged the warp; all stage reads done
            if (lane == 0) MBARRIER_ARRIVE(empty_mb + st * 8);
            gq++;
        }

        // epilogue: combine, bias + tanh, write h in tiled+swizzled hi/lo layout
        char* cblk = jb.C + ((size_t)mt * NT + nt) * A_BLK;
        #pragma unroll
        for (int i = 0; i < 2; i++) {
            const int grow = wm0 + i * 16 + r0;
            #pragma unroll
            for (int j = 0; j < 2; j++) {
                const int col = wn0 + j * 8 + c0;
                const float bv0 = s_bias[col], bv1 = s_bias[col + 1];
                const uint32_t o0 = SWZ((uint32_t)(grow * 128 + col * 2));
                const uint32_t o1 = SWZ((uint32_t)((grow + 8) * 128 + col * 2));
                float t00 = fast_tanh(acc1[i][j][0] + acc2[i][j][0] + bv0);
                float t01 = fast_tanh(acc1[i][j][1] + acc2[i][j][1] + bv1);
                float t10 = fast_tanh(acc1[i][j][2] + acc2[i][j][2] + bv0);
                float t11 = fast_tanh(acc1[i][j][3] + acc2[i][j][3] + bv1);
                uint32_t u0 = pkbf(t00, t01);
                uint32_t u1 = pkbf(t10, t11);
                *(uint32_t*)(cblk + o0) = u0;
                *(uint32_t*)(cblk + o1) = u1;
                float s00 = t00 - __uint_as_float(u0 << 16);
                float s01 = t01 - __uint_as_float(u0 & 0xFFFF0000u);
                float s10 = t10 - __uint_as_float(u1 << 16);
                float s11 = t11 - __uint_as_float(u1 & 0xFFFF0000u);
                *(uint32_t*)(cblk + A_HALF + o0) = pkbf(s00, s01);
                *(uint32_t*)(cblk + A_HALF + o1) = pkbf(s10, s11);
            }
        }
    }
}

// ---------------- classifier (reads tiled h layout) ----------------
__global__ void classifier_kernel(const char* __restrict__ hbase,
                                  const float* __restrict__ Wout,
                                  const float* __restrict__ bout,
                                  float* __restrict__ out) {
    int warp = (blockIdx.x * blockDim.x + threadIdx.x) >> 5;
    int lane = threadIdx.x & 31;
    if (warp >= BATCH * OUTDIM) return;
    int b = warp / OUTDIM, o = warp % OUTDIM;
    const float* wr = Wout + (size_t)o * HID;
    float s = 0.0f;
    for (int k = lane; k < HID; k += 32) {
        size_t blk = ((size_t)(b >> 7) * NT + (k >> 6)) * A_BLK;
        uint32_t off = SWZ((uint32_t)(((b & 127) * 128) + (k & 63) * 2));
        float hv = __bfloat162float(*(const __nv_bfloat16*)(hbase + blk + off))
                 + __bfloat162float(*(const __nv_bfloat16*)(hbase + blk + A_HALF + off));
        s += hv * wr[k];
    }
    #pragma unroll
    for (int off = 16; off; off >>= 1) s += __shfl_down_sync(0xffffffff, s, off);
    if (lane == 0) out[b * OUTDIM + o] = s + bout[o];
}

// ---------------- host ----------------
extern "C" void kernel_launch(void* const* d_in, const int* in_sizes, int n_in,
                              void* d_out, int out_size) {
    const float* xs   = (const float*)d_in[0];
    const float* Wih0 = (const float*)d_in[1];
    const float* Whh0 = (const float*)d_in[2];
    const float* bih0 = (const float*)d_in[3];
    const float* bhh0 = (const float*)d_in[4];
    const float* Wih1 = (const float*)d_in[5];
    const float* Whh1 = (const float*)d_in[6];
    const float* bih1 = (const float*)d_in[7];
    const float* bhh1 = (const float*)d_in[8];
    const float* Wout = (const float*)d_in[9];
    const float* bout = (const float*)d_in[10];
    float* out = (float*)d_out;

    static int attr_done = 0;
    if (!attr_done) {
        cudaFuncSetAttribute(cell_kernel, cudaFuncAttributeMaxDynamicSharedMemorySize,
                             SMEM_BYTES);
        attr_done = 1;
    }

    void* p;
    char *xb, *h0b, *h1b, *wi0, *wh0, *wi1, *wh1;
    cudaGetSymbolAddress(&p, gx);    xb  = (char*)p;
    cudaGetSymbolAddress(&p, gh0);   h0b = (char*)p;
    cudaGetSymbolAddress(&p, gh1);   h1b = (char*)p;
    cudaGetSymbolAddress(&p, gWih0); wi0 = (char*)p;
    cudaGetSymbolAddress(&p, gWhh0); wh0 = (char*)p;
    cudaGetSymbolAddress(&p, gWih1); wi1 = (char*)p;
    cudaGetSymbolAddress(&p, gWhh1); wh1 = (char*)p;

    prep_kernel<<<(unsigned)((NXE + 255) / 256), 256>>>(xs, Wih0, Whh0, Wih1, Whh1);

    const size_t XB = (size_t)MT * A_BLK;

    // t = 0: layer0 only  (h0(-1) = zeros at parity 1)
    {
        Job j0;
        j0.s[0] = { xb, wi0, 1 };
        j0.s[1] = { h0b + PSZ, wh0, NT };
        j0.b1 = bih0; j0.b2 = bhh0;
        j0.C = h0b;
        cell_kernel<<<GRID, TPB, SMEM_BYTES>>>(j0, j0, 0, TILES);
    }

    // t = 1..127: fused h0(t) || h1(t-1); heavy layer1 job first
    for (int t = 1; t < TSTEPS; t++) {
        const size_t pPrev = (size_t)((t - 1) & 1) * PSZ;
        const size_t pCur  = (size_t)(t & 1) * PSZ;
        Job j1;
        j1.s[0] = { h0b + pPrev, wi1, NT };
        j1.s[1] = { h1b + pCur,  wh1, NT };
        j1.b1 = bih1; j1.b2 = bhh1;
        j1.C = h1b + pPrev;
        Job j0;
        j0.s[0] = { xb + (size_t)t * XB, wi0, 1 };
        j0.s[1] = { h0b + pPrev, wh0, NT };
        j0.b1 = bih0; j0.b2 = bhh0;
        j0.C = h0b + pCur;
        cell_kernel<<<GRID, TPB, SMEM_BYTES>>>(j1, j0, t, 2 * TILES);
    }

    // drain: h1(127)
    {
        Job jf;
        jf.s[0] = { h0b + PSZ, wi1, NT };
        jf.s[1] = { h1b,       wh1, NT };
        jf.b1 = bih1; jf.b2 = bhh1;
        jf.C = h1b + PSZ;
        cell_kernel<<<GRID, TPB, SMEM_BYTES>>>(jf, jf, TSTEPS, TILES);
    }

    classifier_kernel<<<(BATCH * OUTDIM * 32 + 255) / 256, 256>>>(
        h1b + PSZ, Wout, bout, out);
}

// round 14
// speedup vs baseline: 1.7017x; 1.0558x over previous
#include <cuda_runtime.h>
#include <cuda_bf16.h>
#include <stdint.h>
#include <math.h>

// ---------------- problem constants ----------------
#define TSTEPS 128
#define BATCH  1024
#define INDIM  47
#define HID    646
#define OUTDIM 5

// ---------------- tiling ----------------
#define MTILE 128
#define NTILE 64
#define KC    64                  // k-chunk (bf16) = 128B row
#define NT    11                  // n-tiles (NPAD 704)
#define MT    8
#define TILES 88                  // per job
#define TPB   256                 // 8 warps: 4(m) x 2(n), warp tile 32x32
#define NWARP 8
#define GRID  148

// tiled-block sizes (bytes)
#define A_HALF 16384              // 128 rows x 128B
#define A_BLK  32768              // hi + lo
#define W_HALF 8192               // 64 rows x 128B
#define W_BLK  16384
#define STAGE_B (A_BLK + W_BLK)   // 49152
#define NSTAGE 4
#define SMEM_BYTES (NSTAGE * STAGE_B + 1024)   // 197632

#define SWZ(x) ((x) ^ (((x) >> 3) & 0x70))

// ---------------- device globals (pre-tiled, pre-swizzled; no allocation) ----
#define PSZ ((size_t)MT * NT * A_BLK)
__device__ __align__(1024) char gx[(size_t)TSTEPS * MT * A_BLK];   // 32MB
__device__ __align__(1024) char gh0[2 * PSZ];
__device__ __align__(1024) char gh1[2 * PSZ];
__device__ __align__(1024) char gWih0[NT * 1 * W_BLK];
__device__ __align__(1024) char gWhh0[NT * NT * W_BLK];
__device__ __align__(1024) char gWih1[NT * NT * W_BLK];
__device__ __align__(1024) char gWhh1[NT * NT * W_BLK];
__device__ unsigned int g_counter[TSTEPS + 2];

// ---------------- PTX helpers ----------------
__device__ __forceinline__ uint32_t pkbf(float lo, float hi) {
    uint32_t r;
    asm("cvt.rn.bf16x2.f32 %0, %1, %2;" : "=r"(r) : "f"(hi), "f"(lo));
    return r;
}
__device__ __forceinline__ float fast_tanh(float x) {
    float e = __expf(2.0f * x);
    return 1.0f - __fdividef(2.0f, e + 1.0f);
}
__device__ __forceinline__ void mma_bf16(float* d, const uint32_t a[4], const uint32_t* b) {
    asm volatile(
        "mma.sync.aligned.m16n8k16.row.col.f32.bf16.bf16.f32 "
        "{%0,%1,%2,%3}, {%4,%5,%6,%7}, {%8,%9}, {%0,%1,%2,%3};"
        : "+f"(d[0]), "+f"(d[1]), "+f"(d[2]), "+f"(d[3])
        : "r"(a[0]), "r"(a[1]), "r"(a[2]), "r"(a[3]), "r"(b[0]), "r"(b[1]));
}
#define LDSM_X4(R, addr) \
    asm volatile("ldmatrix.sync.aligned.m8n8.x4.shared.b16 {%0,%1,%2,%3}, [%4];" \
        : "=r"((R)[0]), "=r"((R)[1]), "=r"((R)[2]), "=r"((R)[3]) : "r"(addr))
#define MBARRIER_INIT(addr, cnt) \
    asm volatile("mbarrier.init.shared.b64 [%0], %1;" :: "r"(addr), "r"(cnt) : "memory")
#define MBARRIER_EXPECT_TX(addr, bytes) \
    asm volatile("mbarrier.arrive.expect_tx.shared.b64 _, [%0], %1;" :: "r"(addr), "r"(bytes) : "memory")
#define MBARRIER_ARRIVE(addr) \
    asm volatile("mbarrier.arrive.shared.b64 _, [%0];" :: "r"(addr) : "memory")
#define MBARRIER_WAIT_PARITY(addr, par) do {                                        \
    uint32_t _mb = (addr), _pa = (par), _dn;                                        \
    asm volatile("{ .reg .pred p; mbarrier.try_wait.parity.acquire.cta.shared::cta.b64 p, [%1], %2; selp.b32 %0, 1, 0, p; }" \
        : "=r"(_dn) : "r"(_mb), "r"(_pa) : "memory");                               \
    if (!_dn) {                                                                     \
        asm volatile("{ .reg .pred P1; WL%=: mbarrier.try_wait.parity.acquire.cta.shared::cta.b64 P1, [%0], %1, 0x989680; @P1 bra.uni WD%=; bra.uni WL%=; WD%=: }" \
            :: "r"(_mb), "r"(_pa) : "memory");                                      \
    }                                                                               \
} while (0)
#define BULK_G2S(dst, src, bytes, mbar) \
    asm volatile("cp.async.bulk.shared::cluster.global.mbarrier::complete_tx::bytes [%0], [%1], %2, [%3];" \
        :: "r"(dst), "l"(src), "r"(bytes), "r"(mbar) : "memory")

// ---------------- preprocessing: split to bf16 hi/lo, tiled + SW128 layout ----
__device__ __forceinline__ void store_split(char* base, uint32_t off, float v, int half_b) {
    __nv_bfloat16 hi = __float2bfloat16(v);
    *(__nv_bfloat16*)(base + off) = hi;
    *(__nv_bfloat16*)(base + half_b + off) = __float2bfloat16(v - __bfloat162float(hi));
}

#define NXE ((long)TSTEPS * MT * 8192)
#define NWHE ((long)NT * NT * 4096)
#define NW0E ((long)NT * 4096)
#define NHZ ((long)2 * PSZ / 16)

__global__ void prep_kernel(const float* __restrict__ xs,
                            const float* __restrict__ Wih0,
                            const float* __restrict__ Whh0,
                            const float* __restrict__ Wih1,
                            const float* __restrict__ Whh1) {
    long i = (long)blockIdx.x * blockDim.x + threadIdx.x;
    if (i < NXE) {
        int bi = (int)(i >> 13), e = (int)(i & 8191);
        int t = bi >> 3, mt = bi & 7, r = e >> 6, k = e & 63;
        float v = (k < INDIM)
            ? xs[((size_t)t * BATCH + mt * 128 + r) * INDIM + k] : 0.0f;
        store_split(gx + (size_t)bi * A_BLK, SWZ(r * 128 + k * 2), v, A_HALF);
    }
    if (i < NWHE) {
        int nt = (int)(i / (NT * 4096)); int rem = (int)(i % (NT * 4096));
        int c = rem >> 12, e = rem & 4095, r = e >> 6, k = e & 63;
        int n = nt * 64 + r, kk = c * 64 + k;
        bool ok = (n < HID) && (kk < HID);
        size_t boff = ((size_t)nt * NT + c) * W_BLK;
        uint32_t soff = SWZ(r * 128 + k * 2);
        store_split(gWhh0 + boff, soff, ok ? Whh0[(size_t)n * HID + kk] : 0.0f, W_HALF);
        store_split(gWih1 + boff, soff, ok ? Wih1[(size_t)n * HID + kk] : 0.0f, W_HALF);
        store_split(gWhh1 + boff, soff, ok ? Whh1[(size_t)n * HID + kk] : 0.0f, W_HALF);
    }
    if (i < NW0E) {
        int nt = (int)(i >> 12), e = (int)(i & 4095), r = e >> 6, k = e & 63;
        int n = nt * 64 + r;
        float v = (n < HID && k < INDIM) ? Wih0[(size_t)n * INDIM + k] : 0.0f;
        store_split(gWih0 + (size_t)nt * W_BLK, SWZ(r * 128 + k * 2), v, W_HALF);
    }
    if (i < NHZ) {
        uint4 z = make_uint4(0, 0, 0, 0);
        ((uint4*)gh0)[i] = z;
        ((uint4*)gh1)[i] = z;
    }
    if (i < TSTEPS + 2) g_counter[i] = 0u;
}

// ---------------- cell kernel ----------------
struct Seg {
    const char* A;   // tiled A blocks: (mt*chunks + c) * A_BLK
    const char* W;   // tiled W blocks: (nt*chunks + c) * W_BLK
    int chunks;
};
struct Job {
    Seg s[2];
    const float *b1, *b2;
    char* C;
};

// producer: wait empty[stage], then expect_tx + 2 bulk copies into stage
__device__ __forceinline__ void issue_at(const Job& jb, int c, int mt, int nt,
                                         uint32_t base, uint32_t full_mb,
                                         uint32_t empty_mb, int g) {
    const int st = g & (NSTAGE - 1);
    const int rnd = g >> 2;
    MBARRIER_WAIT_PARITY(empty_mb + st * 8, (uint32_t)((rnd + 1) & 1));
    const Seg& S = (c < jb.s[0].chunks) ? jb.s[0] : jb.s[1];
    const int cc = (c < jb.s[0].chunks) ? c : c - jb.s[0].chunks;
    const char* Asrc = S.A + ((size_t)mt * S.chunks + cc) * A_BLK;
    const char* Wsrc = S.W + ((size_t)nt * S.chunks + cc) * W_BLK;
    const uint32_t stage = base + st * STAGE_B;
    const uint32_t fmb = full_mb + st * 8;
    MBARRIER_EXPECT_TX(fmb, STAGE_B);
    BULK_G2S(stage, Asrc, A_BLK, fmb);
    BULK_G2S(stage + A_BLK, Wsrc, W_BLK, fmb);
}

__global__ __launch_bounds__(TPB, 1) void cell_kernel(Job jH, Job jL,
                                                      int cidx, int ntiles) {
    extern __shared__ __align__(1024) char dyn[];
    __shared__ __align__(8) uint64_t s_mbar[2 * NSTAGE];
    __shared__ float s_bias[NTILE];
    __shared__ unsigned int s_idx;

    const int tid = threadIdx.x, lane = tid & 31, wid = tid >> 5;
    const int wm0 = (wid & 3) * 32;      // warp m offset (4 m-warps, 32 rows)
    const int wn0 = (wid >> 2) * 32;     // warp n offset (2 n-warps, 32 cols)
    const int r0 = lane >> 2;
    const int c0 = (lane & 3) * 2;
    const bool producer = (tid == 0);

    uint32_t dyn_u32;
    asm("{ .reg .u64 t; cvta.to.shared.u64 t, %1; cvt.u32.u64 %0, t; }"
        : "=r"(dyn_u32) : "l"(dyn));
    const uint32_t base = (dyn_u32 + 1023) & ~1023u;
    uint32_t mb_u32;
    asm("{ .reg .u64 t; cvta.to.shared.u64 t, %1; cvt.u32.u64 %0, t; }"
        : "=r"(mb_u32) : "l"(&s_mbar[0]));
    const uint32_t full_mb = mb_u32;
    const uint32_t empty_mb = mb_u32 + 8 * NSTAGE;

    if (tid == 0) {
        #pragma unroll
        for (int s = 0; s < NSTAGE; s++) {
            MBARRIER_INIT(full_mb + s * 8, 1);        // tx-based
            MBARRIER_INIT(empty_mb + s * 8, NWARP);   // one arrive per warp
        }
    }
    __syncthreads();

    // ldmatrix within-tile swizzled offsets
    const int lt = lane >> 3, lr = lane & 7;
    uint32_t offA[2][4], offB[2][4];
    #pragma unroll
    for (int i = 0; i < 2; i++)
        #pragma unroll
        for (int s = 0; s < 4; s++) {
            int rA = wm0 + i * 16 + (lt & 1) * 8 + lr;
            int cb = s * 32 + (lt >> 1) * 16;
            offA[i][s] = SWZ((uint32_t)(rA * 128 + cb));
        }
    #pragma unroll
    for (int jp = 0; jp < 2; jp++)
        #pragma unroll
        for (int s = 0; s < 4; s++) {
            int rB = wn0 + jp * 16 + (lt >> 1) * 8 + lr;
            int cb = s * 32 + (lt & 1) * 16;
            offB[jp][s] = SWZ((uint32_t)(rB * 128 + cb)) + A_BLK;
        }

    int gq = 0;    // per-warp consumed-chunk cursor
    int gqi = 0;   // producer issued-chunk cursor

    for (;;) {
        if (tid == 0) s_idx = atomicAdd(&g_counter[cidx], 1u);
        __syncthreads();   // s_idx handoff; all warps past prev tile's epilogue/bias
        const unsigned int idx = s_idx;
        if (idx >= (unsigned int)ntiles) break;

        const Job& jb = (idx < TILES) ? jH : jL;
        const int tile = (idx < TILES) ? (int)idx : (int)idx - TILES;
        const int mt = tile / NT;
        const int nt = tile % NT;
        const int n0 = nt * 64;

        if (tid < NTILE) {
            int n = n0 + tid;
            s_bias[tid] = (n < HID) ? (jb.b1[n] + jb.b2[n]) : 0.0f;
        }

        const int nch = jb.s[0].chunks + jb.s[1].chunks;

        if (producer) {
            const int pro = (nch < NSTAGE - 1) ? nch : NSTAGE - 1;
            for (int c = 0; c < pro; c++) {
                issue_at(jb, c, mt, nt, base, full_mb, empty_mb, gqi);
                gqi++;
            }
        }

        // acc[term][i(m16)][jj(n8)][4] : 2x2x4x4 floats per term
        float acc1[2][4][4] = {};
        float acc2[2][4][4] = {};

        for (int c = 0; c < nch; c++) {
            if (producer && c + NSTAGE - 1 < nch) {
                issue_at(jb, c + NSTAGE - 1, mt, nt, base, full_mb, empty_mb, gqi);
                gqi++;
            }
            const int st = gq & (NSTAGE - 1);
            const int rnd = gq >> 2;
            MBARRIER_WAIT_PARITY(full_mb + st * 8, (uint32_t)(rnd & 1));

            const uint32_t sb = base + st * STAGE_B;
            #pragma unroll
            for (int s = 0; s < 4; s++) {
                uint32_t ah[2][4], al[2][4], bh[2][4], bl[2][4];
                #pragma unroll
                for (int i = 0; i < 2; i++) {
                    LDSM_X4(ah[i], sb + offA[i][s]);
                    LDSM_X4(al[i], sb + offA[i][s] + A_HALF);
                }
                #pragma unroll
                for (int jp = 0; jp < 2; jp++) {
                    LDSM_X4(bh[jp], sb + offB[jp][s]);
                    LDSM_X4(bl[jp], sb + offB[jp][s] + W_HALF);
                }
                #pragma unroll
                for (int i = 0; i < 2; i++)
                    #pragma unroll
                    for (int jj = 0; jj < 4; jj++) {
                        const uint32_t* pbh = &bh[jj >> 1][(jj & 1) * 2];
                        const uint32_t* pbl = &bl[jj >> 1][(jj & 1) * 2];
                        mma_bf16(acc1[i][jj], ah[i], pbh);
                        mma_bf16(acc2[i][jj], ah[i], pbl);
                        mma_bf16(acc2[i][jj], al[i], pbh);
                    }
            }
            if (lane == 0) MBARRIER_ARRIVE(empty_mb + st * 8);
            gq++;
        }

        // epilogue: combine, bias + tanh, write h in tiled+swizzled hi/lo layout
        char* cblk = jb.C + ((size_t)mt * NT + nt) * A_BLK;
        #pragma unroll
        for (int i = 0; i < 2; i++) {
            const int grow = wm0 + i * 16 + r0;
            #pragma unroll
            for (int jj = 0; jj < 4; jj++) {
                const int col = wn0 + jj * 8 + c0;
                const float bv0 = s_bias[col], bv1 = s_bias[col + 1];
                const uint32_t o0 = SWZ((uint32_t)(grow * 128 + col * 2));
                const uint32_t o1 = SWZ((uint32_t)((grow + 8) * 128 + col * 2));
                float t00 = fast_tanh(acc1[i][jj][0] + acc2[i][jj][0] + bv0);
                float t01 = fast_tanh(acc1[i][jj][1] + acc2[i][jj][1] + bv1);
                float t10 = fast_tanh(acc1[i][jj][2] + acc2[i][jj][2] + bv0);
                float t11 = fast_tanh(acc1[i][jj][3] + acc2[i][jj][3] + bv1);
                uint32_t u0 = pkbf(t00, t01);
                uint32_t u1 = pkbf(t10, t11);
                *(uint32_t*)(cblk + o0) = u0;
                *(uint32_t*)(cblk + o1) = u1;
                float s00 = t00 - __uint_as_float(u0 << 16);
                float s01 = t01 - __uint_as_float(u0 & 0xFFFF0000u);
                float s10 = t10 - __uint_as_float(u1 << 16);
                float s11 = t11 - __uint_as_float(u1 & 0xFFFF0000u);
                *(uint32_t*)(cblk + A_HALF + o0) = pkbf(s00, s01);
                *(uint32_t*)(cblk + A_HALF + o1) = pkbf(s10, s11);
            }
        }
    }
}

// ---------------- classifier (reads tiled h layout) ----------------
__global__ void classifier_kernel(const char* __restrict__ hbase,
                                  const float* __restrict__ Wout,
                                  const float* __restrict__ bout,
                                  float* __restrict__ out) {
    int warp = (blockIdx.x * blockDim.x + threadIdx.x) >> 5;
    int lane = threadIdx.x & 31;
    if (warp >= BATCH * OUTDIM) return;
    int b = warp / OUTDIM, o = warp % OUTDIM;
    const float* wr = Wout + (size_t)o * HID;
    float s = 0.0f;
    for (int k = lane; k < HID; k += 32) {
        size_t blk = ((size_t)(b >> 7) * NT + (k >> 6)) * A_BLK;
        uint32_t off = SWZ((uint32_t)(((b & 127) * 128) + (k & 63) * 2));
        float hv = __bfloat162float(*(const __nv_bfloat16*)(hbase + blk + off))
                 + __bfloat162float(*(const __nv_bfloat16*)(hbase + blk + A_HALF + off));
        s += hv * wr[k];
    }
    #pragma unroll
    for (int off = 16; off; off >>= 1) s += __shfl_down_sync(0xffffffff, s, off);
    if (lane == 0) out[b * OUTDIM + o] = s + bout[o];
}

// ---------------- host ----------------
extern "C" void kernel_launch(void* const* d_in, const int* in_sizes, int n_in,
                              void* d_out, int out_size) {
    const float* xs   = (const float*)d_in[0];
    const float* Wih0 = (const float*)d_in[1];
    const float* Whh0 = (const float*)d_in[2];
    const float* bih0 = (const float*)d_in[3];
    const float* bhh0 = (const float*)d_in[4];
    const float* Wih1 = (const float*)d_in[5];
    const float* Whh1 = (const float*)d_in[6];
    const float* bih1 = (const float*)d_in[7];
    const float* bhh1 = (const float*)d_in[8];
    const float* Wout = (const float*)d_in[9];
    const float* bout = (const float*)d_in[10];
    float* out = (float*)d_out;

    static int attr_done = 0;
    if (!attr_done) {
        cudaFuncSetAttribute(cell_kernel, cudaFuncAttributeMaxDynamicSharedMemorySize,
                             SMEM_BYTES);
        attr_done = 1;
    }

    void* p;
    char *xb, *h0b, *h1b, *wi0, *wh0, *wi1, *wh1;
    cudaGetSymbolAddress(&p, gx);    xb  = (char*)p;
    cudaGetSymbolAddress(&p, gh0);   h0b = (char*)p;
    cudaGetSymbolAddress(&p, gh1);   h1b = (char*)p;
    cudaGetSymbolAddress(&p, gWih0); wi0 = (char*)p;
    cudaGetSymbolAddress(&p, gWhh0); wh0 = (char*)p;
    cudaGetSymbolAddress(&p, gWih1); wi1 = (char*)p;
    cudaGetSymbolAddress(&p, gWhh1); wh1 = (char*)p;

    prep_kernel<<<(unsigned)((NXE + 255) / 256), 256>>>(xs, Wih0, Whh0, Wih1, Whh1);

    const size_t XB = (size_t)MT * A_BLK;

    // t = 0: layer0 only  (h0(-1) = zeros at parity 1)
    {
        Job j0;
        j0.s[0] = { xb, wi0, 1 };
        j0.s[1] = { h0b + PSZ, wh0, NT };
        j0.b1 = bih0; j0.b2 = bhh0;
        j0.C = h0b;
        cell_kernel<<<GRID, TPB, SMEM_BYTES>>>(j0, j0, 0, TILES);
    }

    // t = 1..127: fused h0(t) || h1(t-1); heavy layer1 job first
    for (int t = 1; t < TSTEPS; t++) {
        const size_t pPrev = (size_t)((t - 1) & 1) * PSZ;
        const size_t pCur  = (size_t)(t & 1) * PSZ;
        Job j1;
        j1.s[0] = { h0b + pPrev, wi1, NT };
        j1.s[1] = { h1b + pCur,  wh1, NT };
        j1.b1 = bih1; j1.b2 = bhh1;
        j1.C = h1b + pPrev;
        Job j0;
        j0.s[0] = { xb + (size_t)t * XB, wi0, 1 };
        j0.s[1] = { h0b + pPrev, wh0, NT };
        j0.b1 = bih0; j0.b2 = bhh0;
        j0.C = h0b + pCur;
        cell_kernel<<<GRID, TPB, SMEM_BYTES>>>(j1, j0, t, 2 * TILES);
    }

    // drain: h1(127)
    {
        Job jf;
        jf.s[0] = { h0b + PSZ, wi1, NT };
        jf.s[1] = { h1b,       wh1, NT };
        jf.b1 = bih1; jf.b2 = bhh1;
        jf.C = h1b + PSZ;
        cell_kernel<<<GRID, TPB, SMEM_BYTES>>>(jf, jf, TSTEPS, TILES);
    }

    classifier_kernel<<<(BATCH * OUTDIM * 32 + 255) / 256, 256>>>(
        h1b + PSZ, Wout, bout, out);
}

// round 15
// speedup vs baseline: 1.7602x; 1.0344x over previous
#include <cuda_runtime.h>
#include <cuda_bf16.h>
#include <stdint.h>
#include <math.h>

// ---------------- problem constants ----------------
#define TSTEPS 128
#define BATCH  1024
#define INDIM  47
#define HID    646
#define OUTDIM 5

// ---------------- tiling ----------------
#define MTILE 128
#define NTILE 64
#define KC    64                  // k-chunk (bf16) = 128B row
#define NT    11                  // n-tiles (NPAD 704)
#define MT    8
#define TILES 88                  // per job
#define TPB   288                 // 8 compute warps (4m x 2n) + 1 producer warp
#define NCWARP 8
#define GRID  148

// tiled-block sizes (bytes)
#define A_HALF 16384              // 128 rows x 128B
#define A_BLK  32768              // hi + lo
#define W_HALF 8192               // 64 rows x 128B
#define W_BLK  16384
#define STAGE_B (A_BLK + W_BLK)   // 49152
#define NSTAGE 4
#define SMEM_BYTES (NSTAGE * STAGE_B + 1024)   // 197632

#define SWZ(x) ((x) ^ (((x) >> 3) & 0x70))

// ---------------- device globals (pre-tiled, pre-swizzled; no allocation) ----
#define PSZ ((size_t)MT * NT * A_BLK)
__device__ __align__(1024) char gx[(size_t)TSTEPS * MT * A_BLK];   // 32MB
__device__ __align__(1024) char gh0[2 * PSZ];
__device__ __align__(1024) char gh1[2 * PSZ];
__device__ __align__(1024) char gWih0[NT * 1 * W_BLK];
__device__ __align__(1024) char gWhh0[NT * NT * W_BLK];
__device__ __align__(1024) char gWih1[NT * NT * W_BLK];
__device__ __align__(1024) char gWhh1[NT * NT * W_BLK];
__device__ unsigned int g_counter[TSTEPS + 2];

// ---------------- PTX helpers ----------------
__device__ __forceinline__ uint32_t pkbf(float lo, float hi) {
    uint32_t r;
    asm("cvt.rn.bf16x2.f32 %0, %1, %2;" : "=r"(r) : "f"(hi), "f"(lo));
    return r;
}
__device__ __forceinline__ float fast_tanh(float x) {
    float e = __expf(2.0f * x);
    return 1.0f - __fdividef(2.0f, e + 1.0f);
}
__device__ __forceinline__ void mma_bf16(float* d, const uint32_t a[4], const uint32_t* b) {
    asm volatile(
        "mma.sync.aligned.m16n8k16.row.col.f32.bf16.bf16.f32 "
        "{%0,%1,%2,%3}, {%4,%5,%6,%7}, {%8,%9}, {%0,%1,%2,%3};"
        : "+f"(d[0]), "+f"(d[1]), "+f"(d[2]), "+f"(d[3])
        : "r"(a[0]), "r"(a[1]), "r"(a[2]), "r"(a[3]), "r"(b[0]), "r"(b[1]));
}
#define LDSM_X4(R, addr) \
    asm volatile("ldmatrix.sync.aligned.m8n8.x4.shared.b16 {%0,%1,%2,%3}, [%4];" \
        : "=r"((R)[0]), "=r"((R)[1]), "=r"((R)[2]), "=r"((R)[3]) : "r"(addr))
#define MBARRIER_INIT(addr, cnt) \
    asm volatile("mbarrier.init.shared.b64 [%0], %1;" :: "r"(addr), "r"(cnt) : "memory")
#define MBARRIER_EXPECT_TX(addr, bytes) \
    asm volatile("mbarrier.arrive.expect_tx.shared.b64 _, [%0], %1;" :: "r"(addr), "r"(bytes) : "memory")
#define MBARRIER_ARRIVE(addr) \
    asm volatile("mbarrier.arrive.shared.b64 _, [%0];" :: "r"(addr) : "memory")
#define MBARRIER_WAIT_PARITY(addr, par) do {                                        \
    uint32_t _mb = (addr), _pa = (par), _dn;                                        \
    asm volatile("{ .reg .pred p; mbarrier.try_wait.parity.acquire.cta.shared::cta.b64 p, [%1], %2; selp.b32 %0, 1, 0, p; }" \
        : "=r"(_dn) : "r"(_mb), "r"(_pa) : "memory");                               \
    if (!_dn) {                                                                     \
        asm volatile("{ .reg .pred P1; WL%=: mbarrier.try_wait.parity.acquire.cta.shared::cta.b64 P1, [%0], %1, 0x989680; @P1 bra.uni WD%=; bra.uni WL%=; WD%=: }" \
            :: "r"(_mb), "r"(_pa) : "memory");                                      \
    }                                                                               \
} while (0)
#define BULK_G2S(dst, src, bytes, mbar) \
    asm volatile("cp.async.bulk.shared::cluster.global.mbarrier::complete_tx::bytes [%0], [%1], %2, [%3];" \
        :: "r"(dst), "l"(src), "r"(bytes), "r"(mbar) : "memory")

// ---------------- preprocessing: split to bf16 hi/lo, tiled + SW128 layout ----
__device__ __forceinline__ void store_split(char* base, uint32_t off, float v, int half_b) {
    __nv_bfloat16 hi = __float2bfloat16(v);
    *(__nv_bfloat16*)(base + off) = hi;
    *(__nv_bfloat16*)(base + half_b + off) = __float2bfloat16(v - __bfloat162float(hi));
}

#define NXE ((long)TSTEPS * MT * 8192)
#define NWHE ((long)NT * NT * 4096)
#define NW0E ((long)NT * 4096)
#define NHZ ((long)2 * PSZ / 16)

__global__ void prep_kernel(const float* __restrict__ xs,
                            const float* __restrict__ Wih0,
                            const float* __restrict__ Whh0,
                            const float* __restrict__ Wih1,
                            const float* __restrict__ Whh1) {
    long i = (long)blockIdx.x * blockDim.x + threadIdx.x;
    if (i < NXE) {
        int bi = (int)(i >> 13), e = (int)(i & 8191);
        int t = bi >> 3, mt = bi & 7, r = e >> 6, k = e & 63;
        float v = (k < INDIM)
            ? xs[((size_t)t * BATCH + mt * 128 + r) * INDIM + k] : 0.0f;
        store_split(gx + (size_t)bi * A_BLK, SWZ(r * 128 + k * 2), v, A_HALF);
    }
    if (i < NWHE) {
        int nt = (int)(i / (NT * 4096)); int rem = (int)(i % (NT * 4096));
        int c = rem >> 12, e = rem & 4095, r = e >> 6, k = e & 63;
        int n = nt * 64 + r, kk = c * 64 + k;
        bool ok = (n < HID) && (kk < HID);
        size_t boff = ((size_t)nt * NT + c) * W_BLK;
        uint32_t soff = SWZ(r * 128 + k * 2);
        store_split(gWhh0 + boff, soff, ok ? Whh0[(size_t)n * HID + kk] : 0.0f, W_HALF);
        store_split(gWih1 + boff, soff, ok ? Wih1[(size_t)n * HID + kk] : 0.0f, W_HALF);
        store_split(gWhh1 + boff, soff, ok ? Whh1[(size_t)n * HID + kk] : 0.0f, W_HALF);
    }
    if (i < NW0E) {
        int nt = (int)(i >> 12), e = (int)(i & 4095), r = e >> 6, k = e & 63;
        int n = nt * 64 + r;
        float v = (n < HID && k < INDIM) ? Wih0[(size_t)n * INDIM + k] : 0.0f;
        store_split(gWih0 + (size_t)nt * W_BLK, SWZ(r * 128 + k * 2), v, W_HALF);
    }
    if (i < NHZ) {
        uint4 z = make_uint4(0, 0, 0, 0);
        ((uint4*)gh0)[i] = z;
        ((uint4*)gh1)[i] = z;
    }
    if (i < TSTEPS + 2) g_counter[i] = 0u;
}

// ---------------- cell kernel ----------------
struct Seg {
    const char* A;   // tiled A blocks: (mt*chunks + c) * A_BLK
    const char* W;   // tiled W blocks: (nt*chunks + c) * W_BLK
    int chunks;
};
struct Job {
    Seg s[2];
    const float *b1, *b2;
    char* C;
};

// producer: wait empty[stage], then expect_tx + 2 bulk copies into stage
__device__ __forceinline__ void issue_at(const Job& jb, int c, int mt, int nt,
                                         uint32_t base, uint32_t full_mb,
                                         uint32_t empty_mb, int g) {
    const int st = g & (NSTAGE - 1);
    const int rnd = g >> 2;
    MBARRIER_WAIT_PARITY(empty_mb + st * 8, (uint32_t)((rnd + 1) & 1));
    const Seg& S = (c < jb.s[0].chunks) ? jb.s[0] : jb.s[1];
    const int cc = (c < jb.s[0].chunks) ? c : c - jb.s[0].chunks;
    const char* Asrc = S.A + ((size_t)mt * S.chunks + cc) * A_BLK;
    const char* Wsrc = S.W + ((size_t)nt * S.chunks + cc) * W_BLK;
    const uint32_t stage = base + st * STAGE_B;
    const uint32_t fmb = full_mb + st * 8;
    MBARRIER_EXPECT_TX(fmb, STAGE_B);
    BULK_G2S(stage, Asrc, A_BLK, fmb);
    BULK_G2S(stage + A_BLK, Wsrc, W_BLK, fmb);
}

// load the 8 LDSM fragments of s-step s into register buffer `buf`
#define LOAD_FRAGS(buf, sb, s) do {                               \
    LDSM_X4(ah[buf][0], (sb) + offA[0][s]);                       \
    LDSM_X4(ah[buf][1], (sb) + offA[1][s]);                       \
    LDSM_X4(al[buf][0], (sb) + offA[0][s] + A_HALF);              \
    LDSM_X4(al[buf][1], (sb) + offA[1][s] + A_HALF);              \
    LDSM_X4(bh[buf][0], (sb) + offB[0][s]);                       \
    LDSM_X4(bh[buf][1], (sb) + offB[1][s]);                       \
    LDSM_X4(bl[buf][0], (sb) + offB[0][s] + W_HALF);              \
    LDSM_X4(bl[buf][1], (sb) + offB[1][s] + W_HALF);              \
} while (0)

__global__ __launch_bounds__(TPB, 1) void cell_kernel(Job jH, Job jL,
                                                      int cidx, int ntiles) {
    extern __shared__ __align__(1024) char dyn[];
    __shared__ __align__(8) uint64_t s_mbar[2 * NSTAGE];
    __shared__ float s_bias[NTILE];
    __shared__ unsigned int s_idx;

    const int tid = threadIdx.x, lane = tid & 31, wid = tid >> 5;
    const bool is_producer = (wid == NCWARP);
    const int wm0 = (wid & 3) * 32;      // compute-warp m offset (4 m-warps)
    const int wn0 = ((wid >> 2) & 1) * 32;   // compute-warp n offset (2 n-warps)
    const int r0 = lane >> 2;
    const int c0 = (lane & 3) * 2;

    uint32_t dyn_u32;
    asm("{ .reg .u64 t; cvta.to.shared.u64 t, %1; cvt.u32.u64 %0, t; }"
        : "=r"(dyn_u32) : "l"(dyn));
    const uint32_t base = (dyn_u32 + 1023) & ~1023u;
    uint32_t mb_u32;
    asm("{ .reg .u64 t; cvta.to.shared.u64 t, %1; cvt.u32.u64 %0, t; }"
        : "=r"(mb_u32) : "l"(&s_mbar[0]));
    const uint32_t full_mb = mb_u32;
    const uint32_t empty_mb = mb_u32 + 8 * NSTAGE;

    if (tid == 0) {
        #pragma unroll
        for (int s = 0; s < NSTAGE; s++) {
            MBARRIER_INIT(full_mb + s * 8, 1);         // tx-based
            MBARRIER_INIT(empty_mb + s * 8, NCWARP);   // one arrive per compute warp
        }
    }
    __syncthreads();

    // ldmatrix within-tile swizzled offsets (compute warps)
    const int lt = lane >> 3, lr = lane & 7;
    uint32_t offA[2][4], offB[2][4];
    #pragma unroll
    for (int i = 0; i < 2; i++)
        #pragma unroll
        for (int s = 0; s < 4; s++) {
            int rA = wm0 + i * 16 + (lt & 1) * 8 + lr;
            int cb = s * 32 + (lt >> 1) * 16;
            offA[i][s] = SWZ((uint32_t)(rA * 128 + cb));
        }
    #pragma unroll
    for (int jp = 0; jp < 2; jp++)
        #pragma unroll
        for (int s = 0; s < 4; s++) {
            int rB = wn0 + jp * 16 + (lt >> 1) * 8 + lr;
            int cb = s * 32 + (lt & 1) * 16;
            offB[jp][s] = SWZ((uint32_t)(rB * 128 + cb)) + A_BLK;
        }

    int gq = 0;    // consumer consumed-chunk cursor
    int gqi = 0;   // producer issued-chunk cursor

    for (;;) {
        if (tid == 0) s_idx = atomicAdd(&g_counter[cidx], 1u);
        __syncthreads();   // s_idx handoff; all warps past prev tile
        const unsigned int idx = s_idx;
        if (idx >= (unsigned int)ntiles) break;

        const Job& jb = (idx < TILES) ? jH : jL;
        const int tile = (idx < TILES) ? (int)idx : (int)idx - TILES;
        const int mt = tile / NT;
        const int nt = tile % NT;
        const int n0 = nt * 64;
        const int nch = jb.s[0].chunks + jb.s[1].chunks;

        if (is_producer) {
            // dedicated producer: issue every chunk, bounded by empty ring
            if (lane == 0) {
                for (int c = 0; c < nch; c++) {
                    issue_at(jb, c, mt, nt, base, full_mb, empty_mb, gqi + c);
                }
            }
            gqi += nch;
            continue;   // to tile-top __syncthreads
        }

        // ---- compute warps ----
        if (tid < NTILE) {
            int n = n0 + tid;
            s_bias[tid] = (n < HID) ? (jb.b1[n] + jb.b2[n]) : 0.0f;
        }

        float acc1[2][4][4] = {};
        float acc2[2][4][4] = {};

        for (int c = 0; c < nch; c++) {
            const int st = gq & (NSTAGE - 1);
            const int rnd = gq >> 2;
            MBARRIER_WAIT_PARITY(full_mb + st * 8, (uint32_t)(rnd & 1));

            const uint32_t sb = base + st * STAGE_B;
            uint32_t ah[2][2][4], al[2][2][4], bh[2][2][4], bl[2][2][4];
            LOAD_FRAGS(0, sb, 0);
            #pragma unroll
            for (int s = 0; s < 4; s++) {
                const int cur = s & 1;
                if (s < 3) {
                    const int nxt = (s + 1) & 1;
                    switch (s + 1) {   // constant index for register allocation
                        case 1: LOAD_FRAGS(1, sb, 1); break;
                        case 2: LOAD_FRAGS(0, sb, 2); break;
                        default: LOAD_FRAGS(1, sb, 3); break;
                    }
                    (void)nxt;
                }
                // acc1 (8 independent), then acc2 term1 (8), then acc2 term2 (8)
                #pragma unroll
                for (int i = 0; i < 2; i++)
                    #pragma unroll
                    for (int jj = 0; jj < 4; jj++)
                        mma_bf16(acc1[i][jj], ah[cur][i], &bh[cur][jj >> 1][(jj & 1) * 2]);
                #pragma unroll
                for (int i = 0; i < 2; i++)
                    #pragma unroll
                    for (int jj = 0; jj < 4; jj++)
                        mma_bf16(acc2[i][jj], ah[cur][i], &bl[cur][jj >> 1][(jj & 1) * 2]);
                #pragma unroll
                for (int i = 0; i < 2; i++)
                    #pragma unroll
                    for (int jj = 0; jj < 4; jj++)
                        mma_bf16(acc2[i][jj], al[cur][i], &bh[cur][jj >> 1][(jj & 1) * 2]);
            }
            if (lane == 0) MBARRIER_ARRIVE(empty_mb + st * 8);
            gq++;
        }

        // epilogue: combine, bias + tanh, write h in tiled+swizzled hi/lo layout
        char* cblk = jb.C + ((size_t)mt * NT + nt) * A_BLK;
        #pragma unroll
        for (int i = 0; i < 2; i++) {
            const int grow = wm0 + i * 16 + r0;
            #pragma unroll
            for (int jj = 0; jj < 4; jj++) {
                const int col = wn0 + jj * 8 + c0;
                const float bv0 = s_bias[col], bv1 = s_bias[col + 1];
                const uint32_t o0 = SWZ((uint32_t)(grow * 128 + col * 2));
                const uint32_t o1 = SWZ((uint32_t)((grow + 8) * 128 + col * 2));
                float t00 = fast_tanh(acc1[i][jj][0] + acc2[i][jj][0] + bv0);
                float t01 = fast_tanh(acc1[i][jj][1] + acc2[i][jj][1] + bv1);
                float t10 = fast_tanh(acc1[i][jj][2] + acc2[i][jj][2] + bv0);
                float t11 = fast_tanh(acc1[i][jj][3] + acc2[i][jj][3] + bv1);
                uint32_t u0 = pkbf(t00, t01);
                uint32_t u1 = pkbf(t10, t11);
                *(uint32_t*)(cblk + o0) = u0;
                *(uint32_t*)(cblk + o1) = u1;
                float s00 = t00 - __uint_as_float(u0 << 16);
                float s01 = t01 - __uint_as_float(u0 & 0xFFFF0000u);
                float s10 = t10 - __uint_as_float(u1 << 16);
                float s11 = t11 - __uint_as_float(u1 & 0xFFFF0000u);
                *(uint32_t*)(cblk + A_HALF + o0) = pkbf(s00, s01);
                *(uint32_t*)(cblk + A_HALF + o1) = pkbf(s10, s11);
            }
        }
    }
}

// ---------------- classifier (reads tiled h layout) ----------------
__global__ void classifier_kernel(const char* __restrict__ hbase,
                                  const float* __restrict__ Wout,
                                  const float* __restrict__ bout,
                                  float* __restrict__ out) {
    int warp = (blockIdx.x * blockDim.x + threadIdx.x) >> 5;
    int lane = threadIdx.x & 31;
    if (warp >= BATCH * OUTDIM) return;
    int b = warp / OUTDIM, o = warp % OUTDIM;
    const float* wr = Wout + (size_t)o * HID;
    float s = 0.0f;
    for (int k = lane; k < HID; k += 32) {
        size_t blk = ((size_t)(b >> 7) * NT + (k >> 6)) * A_BLK;
        uint32_t off = SWZ((uint32_t)(((b & 127) * 128) + (k & 63) * 2));
        float hv = __bfloat162float(*(const __nv_bfloat16*)(hbase + blk + off))
                 + __bfloat162float(*(const __nv_bfloat16*)(hbase + blk + A_HALF + off));
        s += hv * wr[k];
    }
    #pragma unroll
    for (int off = 16; off; off >>= 1) s += __shfl_down_sync(0xffffffff, s, off);
    if (lane == 0) out[b * OUTDIM + o] = s + bout[o];
}

// ---------------- host ----------------
extern "C" void kernel_launch(void* const* d_in, const int* in_sizes, int n_in,
                              void* d_out, int out_size) {
    const float* xs   = (const float*)d_in[0];
    const float* Wih0 = (const float*)d_in[1];
    const float* Whh0 = (const float*)d_in[2];
    const float* bih0 = (const float*)d_in[3];
    const float* bhh0 = (const float*)d_in[4];
    const float* Wih1 = (const float*)d_in[5];
    const float* Whh1 = (const float*)d_in[6];
    const float* bih1 = (const float*)d_in[7];
    const float* bhh1 = (const float*)d_in[8];
    const float* Wout = (const float*)d_in[9];
    const float* bout = (const float*)d_in[10];
    float* out = (float*)d_out;

    static int attr_done = 0;
    if (!attr_done) {
        cudaFuncSetAttribute(cell_kernel, cudaFuncAttributeMaxDynamicSharedMemorySize,
                             SMEM_BYTES);
        attr_done = 1;
    }

    void* p;
    char *xb, *h0b, *h1b, *wi0, *wh0, *wi1, *wh1;
    cudaGetSymbolAddress(&p, gx);    xb  = (char*)p;
    cudaGetSymbolAddress(&p, gh0);   h0b = (char*)p;
    cudaGetSymbolAddress(&p, gh1);   h1b = (char*)p;
    cudaGetSymbolAddress(&p, gWih0); wi0 = (char*)p;
    cudaGetSymbolAddress(&p, gWhh0); wh0 = (char*)p;
    cudaGetSymbolAddress(&p, gWih1); wi1 = (char*)p;
    cudaGetSymbolAddress(&p, gWhh1); wh1 = (char*)p;

    prep_kernel<<<(unsigned)((NXE + 255) / 256), 256>>>(xs, Wih0, Whh0, Wih1, Whh1);

    const size_t XB = (size_t)MT * A_BLK;

    // t = 0: layer0 only  (h0(-1) = zeros at parity 1)
    {
        Job j0;
        j0.s[0] = { xb, wi0, 1 };
        j0.s[1] = { h0b + PSZ, wh0, NT };
        j0.b1 = bih0; j0.b2 = bhh0;
        j0.C = h0b;
        cell_kernel<<<GRID, TPB, SMEM_BYTES>>>(j0, j0, 0, TILES);
    }

    // t = 1..127: fused h0(t) || h1(t-1); heavy layer1 job first
    for (int t = 1; t < TSTEPS; t++) {
        const size_t pPrev = (size_t)((t - 1) & 1) * PSZ;
        const size_t pCur  = (size_t)(t & 1) * PSZ;
        Job j1;
        j1.s[0] = { h0b + pPrev, wi1, NT };
        j1.s[1] = { h1b + pCur,  wh1, NT };
        j1.b1 = bih1; j1.b2 = bhh1;
        j1.C = h1b + pPrev;
        Job j0;
        j0.s[0] = { xb + (size_t)t * XB, wi0, 1 };
        j0.s[1] = { h0b + pPrev, wh0, NT };
        j0.b1 = bih0; j0.b2 = bhh0;
        j0.C = h0b + pCur;
        cell_kernel<<<GRID, TPB, SMEM_BYTES>>>(j1, j0, t, 2 * TILES);
    }

    // drain: h1(127)
    {
        Job jf;
        jf.s[0] = { h0b + PSZ, wi1, NT };
        jf.s[1] = { h1b,       wh1, NT };
        jf.b1 = bih1; jf.b2 = bhh1;
        jf.C = h1b + PSZ;
        cell_kernel<<<GRID, TPB, SMEM_BYTES>>>(jf, jf, TSTEPS, TILES);
    }

    classifier_kernel<<<(BATCH * OUTDIM * 32 + 255) / 256, 256>>>(
        h1b + PSZ, Wout, bout, out);
}